// round 3
// baseline (speedup 1.0000x reference)
#include <cuda_runtime.h>
#include <cuda_fp16.h>

#define B_ 512
#define S_ 168
#define F_ 12
#define H_ 128
#define U_ 256
#define O_ 3
#define NB 4

// ---------------- device scratch (no allocations allowed) ----------------
__device__ uint2 g_W0q[35 * 256];     // layer0 weights, [k4][u], 4 halves per entry
__device__ uint2 g_W1q[64 * 256];     // layer1 weights
__device__ uint2 g_Hq[64 * 384];      // merged head weights (ff1 | ff2 | ta+tb)
__device__ float g_bh[384];           // merged head bias
__device__ float g_T[3 * S_ * S_];    // collapsed _sff operators per layer
__device__ float g_mean[B_ * F_];
__device__ float g_x1[B_ * S_ * F_];
__device__ float g_x2[B_ * S_ * O_];
__device__ float g_x3[B_ * S_ * O_];
__device__ float g_hs[B_ * S_ * H_];
__device__ float g_r1[B_ * S_ * O_];

// ---------------- helpers ----------------
__device__ __forceinline__ float siluf(float x) {
    return __fdividef(x, 1.f + __expf(-x));
}
__device__ __forceinline__ float sigf(float x) {
    return __fdividef(1.f, 1.f + __expf(-x));
}
__device__ __forceinline__ uint2 pack4(float a, float b, float c, float d) {
    __half2 lo = __halves2half2(__float2half_rn(a), __float2half_rn(b));
    __half2 hi = __halves2half2(__float2half_rn(c), __float2half_rn(d));
    uint2 r;
    r.x = *reinterpret_cast<unsigned*>(&lo);
    r.y = *reinterpret_cast<unsigned*>(&hi);
    return r;
}
__device__ __forceinline__ void mac4(const uint2 w, const float4 a, float& acc) {
    float2 fa = __half22float2(*reinterpret_cast<const __half2*>(&w.x));
    float2 fb = __half22float2(*reinterpret_cast<const __half2*>(&w.y));
    acc = fmaf(fa.x, a.x, acc);
    acc = fmaf(fa.y, a.y, acc);
    acc = fmaf(fb.x, a.z, acc);
    acc = fmaf(fb.y, a.w, acc);
}

// ---------------- weight repack ----------------
__global__ void k_prep(const float* __restrict__ Wb0, const float* __restrict__ Wb1,
                       const float* __restrict__ Wff1, const float* __restrict__ Wff2,
                       const float* __restrict__ Wta, const float* __restrict__ Wtb,
                       const float* __restrict__ bff1, const float* __restrict__ bff2,
                       const float* __restrict__ bta, const float* __restrict__ btb) {
    int idx = blockIdx.x * blockDim.x + threadIdx.x;
    const int N0 = 35 * 256, N1 = 64 * 256, NH = 64 * 384;
    if (idx < N0) {
        int k4 = idx >> 8, u = idx & 255;
        float w[4];
#pragma unroll
        for (int j = 0; j < 4; j++) {
            int k = k4 * 4 + j;
            w[j] = (k < 140) ? Wb0[u * 140 + k] : 0.f;
        }
        g_W0q[idx] = pack4(w[0], w[1], w[2], w[3]);
    } else if (idx < N0 + N1) {
        int i = idx - N0;
        int k4 = i >> 8, u = i & 255;
        const float* p = Wb1 + u * 256 + k4 * 4;
        g_W1q[i] = pack4(p[0], p[1], p[2], p[3]);
    } else if (idx < N0 + N1 + NH) {
        int i = idx - N0 - N1;
        int k4 = i / 384, j = i % 384;
        float w[4];
#pragma unroll
        for (int jj = 0; jj < 4; jj++) {
            int k = k4 * 4 + jj;
            if (j < 128)       w[jj] = Wff1[j * 256 + k];
            else if (j < 256)  w[jj] = Wff2[(j - 128) * 256 + k];
            else               w[jj] = Wta[(j - 256) * 256 + k] + Wtb[(j - 256) * 256 + k];
        }
        g_Hq[i] = pack4(w[0], w[1], w[2], w[3]);
    } else if (idx < N0 + N1 + NH + 384) {
        int j = idx - N0 - N1 - NH;
        float b;
        if (j < 128)      b = bff1[j];
        else if (j < 256) b = bff2[j - 128];
        else              b = bta[j - 256] + btb[j - 256];
        g_bh[j] = b;
    }
}

// ---------------- build collapsed _sff operators ----------------
__device__ __forceinline__ float sff_contrib(const float* __restrict__ conv,
                                             const float* __restrict__ lin,
                                             int p, int seg, int pad, int so, int si) {
    int phase = so % p, q = so / p;
    float acc = 0.f;
    for (int kk = 0; kk < seg; ++kk) {
        int d = si - (kk * p + phase);
        float c = 0.f;
        if (d >= -pad && d <= pad) c = conv[d + pad];
        if (d == 0) c += 1.f;
        acc += lin[q * seg + kk] * c;
    }
    return acc;
}

__global__ void k_build_T(const float* __restrict__ c3, const float* __restrict__ l3,
                          const float* __restrict__ c6, const float* __restrict__ l6,
                          const float* __restrict__ c12, const float* __restrict__ l12,
                          const float* __restrict__ c24, const float* __restrict__ l24) {
    int idx = blockIdx.x * blockDim.x + threadIdx.x;
    if (idx >= 3 * S_ * S_) return;
    int L = idx / (S_ * S_);
    int r = idx % (S_ * S_);
    int so = r / S_, si = r % S_;
    float a = sff_contrib(c3  + L * 3,  l3  + L * 56 * 56, 3, 56, 1, so, si)
            + sff_contrib(c6  + L * 7,  l6  + L * 28 * 28, 6, 28, 3, so, si)
            + sff_contrib(c12 + L * 13, l12 + L * 14 * 14, 12, 14, 6, so, si)
            + sff_contrib(c24 + L * 25, l24 + L * 7 * 7,  24, 7, 12, so, si);
    g_T[idx] = 0.25f * a;
}

// ---------------- per-(b,f) sequence mean ----------------
__global__ void k_mean(const float* __restrict__ x) {
    int w = (blockIdx.x * blockDim.x + threadIdx.x) >> 5;
    int lane = threadIdx.x & 31;
    if (w >= B_ * F_) return;
    const float* p = x + w * S_;   // x[b][0][f][:]  (w = b*F + f)
    float s = 0.f;
    for (int i = lane; i < S_; i += 32) s += p[i];
#pragma unroll
    for (int o = 16; o; o >>= 1) s += __shfl_xor_sync(0xffffffffu, s, o);
    if (!lane) g_mean[w] = s * (1.f / (float)S_);
}

// ---------------- x1 = T0 @ (xs - mean), per batch ----------------
__global__ void k_x1(const float* __restrict__ x) {
    __shared__ float xs[S_][F_];
    int b = blockIdx.x, t = threadIdx.x;
    for (int i = t; i < S_ * F_; i += blockDim.x) {
        int si = i / F_, f = i % F_;
        xs[si][f] = x[b * F_ * S_ + f * S_ + si] - g_mean[b * F_ + f];
    }
    __syncthreads();
    if (t < S_) {
        float acc[F_];
#pragma unroll
        for (int f = 0; f < F_; f++) acc[f] = 0.f;
        const float* Trow = g_T + t * S_;
        for (int si = 0; si < S_; ++si) {
            float tw = Trow[si];
#pragma unroll
            for (int f = 0; f < F_; f++) acc[f] = fmaf(tw, xs[si][f], acc[f]);
        }
        float* o = g_x1 + (b * S_ + t) * F_;
#pragma unroll
        for (int f = 0; f < F_; f++) o[f] = acc[f];
    }
}

// ---------------- x2 = T1 @ xin3,  x3 = T2 @ xin3 ----------------
__global__ void k_x23() {
    __shared__ float xi[S_][3];
    int b = blockIdx.x, t = threadIdx.x;
    for (int i = t; i < S_ * 3; i += blockDim.x) {
        int s = i / 3, c = i % 3;
        xi[s][c] = g_x1[(b * S_ + s) * F_ + c];
    }
    __syncthreads();
    if (t < S_) {
        float a2[3] = {0.f, 0.f, 0.f};
        float a3[3] = {0.f, 0.f, 0.f};
        const float* T1r = g_T + S_ * S_ + t * S_;
        const float* T2r = g_T + 2 * S_ * S_ + t * S_;
        for (int si = 0; si < S_; ++si) {
            float t1 = T1r[si], t2 = T2r[si];
#pragma unroll
            for (int c = 0; c < 3; c++) {
                a2[c] = fmaf(t1, xi[si][c], a2[c]);
                a3[c] = fmaf(t2, xi[si][c], a3[c]);
            }
        }
#pragma unroll
        for (int c = 0; c < 3; c++) {
            g_x2[(b * S_ + t) * 3 + c] = a2[c];
            g_x3[(b * S_ + t) * 3 + c] = a3[c];
        }
    }
}

// ---------------- the CfC recurrence: 128 CTAs x 4 batch rows ----------------
__global__ void __launch_bounds__(256, 1) k_rnn(const float* __restrict__ bb0,
                                                const float* __restrict__ bb1) {
    __shared__ __align__(16) float in_s[NB][140];
    __shared__ __align__(16) float za[NB][256];
    __shared__ __align__(16) float zb[NB][256];
    __shared__ __align__(16) float hd[NB][384];
    const int t = threadIdx.x;
    const int bb = blockIdx.x * NB;
    const float rb0 = bb0[t], rb1 = bb1[t];
    const float rh1 = g_bh[t];
    const float rh2 = (t < 128) ? g_bh[256 + t] : 0.f;

    for (int i = t; i < NB * 140; i += 256) (&in_s[0][0])[i] = 0.f;
    __syncthreads();

    for (int step = 0; step < S_; ++step) {
        // bring in x_t (12 features per row); h part already in in_s
        if (t < NB * F_) {
            int r = t / F_, f = t - r * F_;
            in_s[r][f] = g_x1[(bb + r) * S_ * F_ + step * F_ + f];
        }
        __syncthreads();

        // ---- layer 0: 140 -> 256, silu ----
        {
            float a0 = rb0, a1 = rb0, a2 = rb0, a3 = rb0;
#pragma unroll 5
            for (int k4 = 0; k4 < 35; ++k4) {
                uint2 w = g_W0q[k4 * 256 + t];
                mac4(w, *(const float4*)&in_s[0][k4 * 4], a0);
                mac4(w, *(const float4*)&in_s[1][k4 * 4], a1);
                mac4(w, *(const float4*)&in_s[2][k4 * 4], a2);
                mac4(w, *(const float4*)&in_s[3][k4 * 4], a3);
            }
            za[0][t] = siluf(a0);
            za[1][t] = siluf(a1);
            za[2][t] = siluf(a2);
            za[3][t] = siluf(a3);
        }
        __syncthreads();

        // ---- layer 1: 256 -> 256, silu ----
        {
            float a0 = rb1, a1 = rb1, a2 = rb1, a3 = rb1;
#pragma unroll 4
            for (int k4 = 0; k4 < 64; ++k4) {
                uint2 w = g_W1q[k4 * 256 + t];
                mac4(w, *(const float4*)&za[0][k4 * 4], a0);
                mac4(w, *(const float4*)&za[1][k4 * 4], a1);
                mac4(w, *(const float4*)&za[2][k4 * 4], a2);
                mac4(w, *(const float4*)&za[3][k4 * 4], a3);
            }
            zb[0][t] = siluf(a0);
            zb[1][t] = siluf(a1);
            zb[2][t] = siluf(a2);
            zb[3][t] = siluf(a3);
        }
        __syncthreads();

        // ---- merged head: 256 -> 384 (ff1 | ff2 | gate). threads <128 take two outputs ----
        {
            float a0 = rh1, a1 = rh1, a2 = rh1, a3 = rh1;
            if (t < 128) {
                float b0v = rh2, b1v = rh2, b2v = rh2, b3v = rh2;
#pragma unroll 4
                for (int k4 = 0; k4 < 64; ++k4) {
                    float4 x0 = *(const float4*)&zb[0][k4 * 4];
                    float4 x1v = *(const float4*)&zb[1][k4 * 4];
                    float4 x2v = *(const float4*)&zb[2][k4 * 4];
                    float4 x3v = *(const float4*)&zb[3][k4 * 4];
                    uint2 w1 = g_Hq[k4 * 384 + t];
                    uint2 w2 = g_Hq[k4 * 384 + 256 + t];
                    mac4(w1, x0, a0);  mac4(w1, x1v, a1);
                    mac4(w1, x2v, a2); mac4(w1, x3v, a3);
                    mac4(w2, x0, b0v);  mac4(w2, x1v, b1v);
                    mac4(w2, x2v, b2v); mac4(w2, x3v, b3v);
                }
                hd[0][256 + t] = b0v;
                hd[1][256 + t] = b1v;
                hd[2][256 + t] = b2v;
                hd[3][256 + t] = b3v;
            } else {
#pragma unroll 4
                for (int k4 = 0; k4 < 64; ++k4) {
                    uint2 w1 = g_Hq[k4 * 384 + t];
                    mac4(w1, *(const float4*)&zb[0][k4 * 4], a0);
                    mac4(w1, *(const float4*)&zb[1][k4 * 4], a1);
                    mac4(w1, *(const float4*)&zb[2][k4 * 4], a2);
                    mac4(w1, *(const float4*)&zb[3][k4 * 4], a3);
                }
            }
            hd[0][t] = a0;
            hd[1][t] = a1;
            hd[2][t] = a2;
            hd[3][t] = a3;
        }
        __syncthreads();

        // ---- combine: h = ff1 + sig*(ff2 - ff1); feed back + store ----
        if (t < 128) {
#pragma unroll
            for (int r = 0; r < NB; ++r) {
                float f1 = tanhf(hd[r][t]);
                float f2 = tanhf(hd[r][128 + t]);
                float s  = sigf(hd[r][256 + t]);
                float h = f1 + s * (f2 - f1);
                in_s[r][F_ + t] = h;
                g_hs[((bb + r) * S_ + step) * H_ + t] = h;
            }
        }
        // no trailing sync needed: next iteration's top barrier orders these writes
    }
}

// ---------------- readout: r1 = hs @ Wfc^T + bfc + x3 ----------------
__global__ void k_readout(const float* __restrict__ Wfc, const float* __restrict__ bfc) {
    int gw = (blockIdx.x * blockDim.x + threadIdx.x) >> 5;
    int lane = threadIdx.x & 31;
    if (gw >= B_ * S_) return;
    const float* h = g_hs + gw * H_;
    float a0 = 0.f, a1 = 0.f, a2 = 0.f;
    for (int i = lane; i < H_; i += 32) {
        float hv = h[i];
        a0 = fmaf(hv, Wfc[i], a0);
        a1 = fmaf(hv, Wfc[128 + i], a1);
        a2 = fmaf(hv, Wfc[256 + i], a2);
    }
#pragma unroll
    for (int o = 16; o; o >>= 1) {
        a0 += __shfl_xor_sync(0xffffffffu, a0, o);
        a1 += __shfl_xor_sync(0xffffffffu, a1, o);
        a2 += __shfl_xor_sync(0xffffffffu, a2, o);
    }
    if (!lane) {
        g_r1[gw * 3 + 0] = a0 + bfc[0] + g_x3[gw * 3 + 0];
        g_r1[gw * 3 + 1] = a1 + bfc[1] + g_x3[gw * 3 + 1];
        g_r1[gw * 3 + 2] = a2 + bfc[2] + g_x3[gw * 3 + 2];
    }
}

// ---------------- final: out[b,p,c] = sum_s r1[b,s,c]*Wfits[c,p,s] + mean[b,c] + x2 ----------------
__global__ void k_final(const float* __restrict__ Wfits, float* __restrict__ out) {
    __shared__ float r1s[S_][3];
    int b = blockIdx.x, t = threadIdx.x;
    for (int i = t; i < S_ * 3; i += blockDim.x) (&r1s[0][0])[i] = g_r1[b * S_ * 3 + i];
    __syncthreads();
    if (t < S_) {
        float a0 = g_mean[b * F_ + 0] + g_x2[(b * S_ + t) * 3 + 0];
        float a1 = g_mean[b * F_ + 1] + g_x2[(b * S_ + t) * 3 + 1];
        float a2 = g_mean[b * F_ + 2] + g_x2[(b * S_ + t) * 3 + 2];
        const float* w0 = Wfits + 0 * S_ * S_ + t * S_;
        const float* w1 = Wfits + 1 * S_ * S_ + t * S_;
        const float* w2 = Wfits + 2 * S_ * S_ + t * S_;
        for (int s = 0; s < S_; ++s) {
            a0 = fmaf(r1s[s][0], w0[s], a0);
            a1 = fmaf(r1s[s][1], w1[s], a1);
            a2 = fmaf(r1s[s][2], w2[s], a2);
        }
        float* o = out + (b * S_ + t) * 3;
        o[0] = a0;
        o[1] = a1;
        o[2] = a2;
    }
}

// ---------------- launch ----------------
extern "C" void kernel_launch(void* const* d_in, const int* in_sizes, int n_in,
                              void* d_out, int out_size) {
    const float* x     = (const float*)d_in[0];
    const float* c3    = (const float*)d_in[1];
    const float* l3    = (const float*)d_in[2];
    const float* c6    = (const float*)d_in[3];
    const float* l6    = (const float*)d_in[4];
    const float* c12   = (const float*)d_in[5];
    const float* l12   = (const float*)d_in[6];
    const float* c24   = (const float*)d_in[7];
    const float* l24   = (const float*)d_in[8];
    const float* Wb0   = (const float*)d_in[9];
    const float* bb0   = (const float*)d_in[10];
    const float* Wb1   = (const float*)d_in[11];
    const float* bb1   = (const float*)d_in[12];
    const float* Wff1  = (const float*)d_in[13];
    const float* bff1  = (const float*)d_in[14];
    const float* Wff2  = (const float*)d_in[15];
    const float* bff2  = (const float*)d_in[16];
    const float* Wta   = (const float*)d_in[17];
    const float* bta   = (const float*)d_in[18];
    const float* Wtb   = (const float*)d_in[19];
    const float* btb   = (const float*)d_in[20];
    const float* Wfc   = (const float*)d_in[21];
    const float* bfc   = (const float*)d_in[22];
    const float* Wfits = (const float*)d_in[23];
    float* out = (float*)d_out;

    k_prep<<<(50304 + 255) / 256, 256>>>(Wb0, Wb1, Wff1, Wff2, Wta, Wtb,
                                         bff1, bff2, bta, btb);
    k_build_T<<<(3 * S_ * S_ + 255) / 256, 256>>>(c3, l3, c6, l6, c12, l12, c24, l24);
    k_mean<<<(B_ * F_ * 32 + 255) / 256, 256>>>(x);
    k_x1<<<B_, 192>>>(x);
    k_x23<<<B_, 192>>>();
    k_rnn<<<B_ / NB, 256>>>(bb0, bb1);
    k_readout<<<(B_ * S_ * 32 + 255) / 256, 256>>>(Wfc, bfc);
    k_final<<<B_, 192>>>(Wfits, out);
}

// round 4
// speedup vs baseline: 1.4327x; 1.4327x over previous
#include <cuda_runtime.h>
#include <cuda_fp16.h>

#define B_ 512
#define S_ 168
#define F_ 12
#define H_ 128
#define U_ 256
#define O_ 3
#define NB 4
#define S2_ (S_ * S_)

typedef unsigned long long u64;

// ---------------- device scratch ----------------
__device__ uint2 g_W0q[35 * 256];     // layer0 [k4][u]
__device__ uint2 g_W1q[64 * 256];     // layer1 [k4][u]
__device__ uint2 g_Hq[64 * 384];      // merged head [k4][j]
__device__ float g_bh[384];
__device__ float g_T[3 * S2_];        // TRANSPOSED: [L][si][so]
__device__ float g_WfT[3 * S2_];      // TRANSPOSED: [c][s][p]
__device__ float g_mean[B_ * F_];
__device__ float g_x1[B_ * S_ * F_];
__device__ float g_x2[B_ * S_ * O_];
__device__ float g_x3[B_ * S_ * O_];
__device__ float g_hs[B_ * S_ * H_];

// ---------------- f32x2 helpers ----------------
__device__ __forceinline__ u64 dup2(float w) {
    u64 r;
    asm("mov.b64 %0, {%1, %2};" : "=l"(r) : "f"(w), "f"(w));
    return r;
}
__device__ __forceinline__ u64 fma2(u64 a, u64 b, u64 c) {
    u64 d;
    asm("fma.rn.f32x2 %0, %1, %2, %3;" : "=l"(d) : "l"(a), "l"(b), "l"(c));
    return d;
}
__device__ __forceinline__ float2 unp(u64 v) {
    float2 f;
    asm("mov.b64 {%0, %1}, %2;" : "=f"(f.x), "=f"(f.y) : "l"(v));
    return f;
}

__device__ __forceinline__ float siluf(float x) {
    return __fdividef(x, 1.f + __expf(-x));
}
__device__ __forceinline__ float sigf(float x) {
    return __fdividef(1.f, 1.f + __expf(-x));
}
__device__ __forceinline__ float tanhf_fast(float x) {
    float e = __expf(2.f * x);
    return 1.f - __fdividef(2.f, e + 1.f);
}

__device__ __forceinline__ uint2 pack4(float a, float b, float c, float d) {
    __half2 lo = __halves2half2(__float2half_rn(a), __float2half_rn(b));
    __half2 hi = __halves2half2(__float2half_rn(c), __float2half_rn(d));
    uint2 r;
    r.x = *reinterpret_cast<unsigned*>(&lo);
    r.y = *reinterpret_cast<unsigned*>(&hi);
    return r;
}

// one weight uint2 (4 k), acts = 4 float4 (rows packed per k)
__device__ __forceinline__ void MAC4(uint2 wv, const ulonglong2* __restrict__ acts,
                                     u64& a01, u64& a23) {
    float2 wA = __half22float2(*reinterpret_cast<const __half2*>(&wv.x));
    float2 wB = __half22float2(*reinterpret_cast<const __half2*>(&wv.y));
    u64 w0 = dup2(wA.x), w1 = dup2(wA.y), w2 = dup2(wB.x), w3 = dup2(wB.y);
    ulonglong2 v0 = acts[0], v1 = acts[1], v2 = acts[2], v3 = acts[3];
    a01 = fma2(w0, v0.x, a01); a23 = fma2(w0, v0.y, a23);
    a01 = fma2(w1, v1.x, a01); a23 = fma2(w1, v1.y, a23);
    a01 = fma2(w2, v2.x, a01); a23 = fma2(w2, v2.y, a23);
    a01 = fma2(w3, v3.x, a01); a23 = fma2(w3, v3.y, a23);
}
__device__ __forceinline__ void MAC4v(uint2 wv, ulonglong2 v0, ulonglong2 v1,
                                      ulonglong2 v2, ulonglong2 v3,
                                      u64& a01, u64& a23) {
    float2 wA = __half22float2(*reinterpret_cast<const __half2*>(&wv.x));
    float2 wB = __half22float2(*reinterpret_cast<const __half2*>(&wv.y));
    u64 w0 = dup2(wA.x), w1 = dup2(wA.y), w2 = dup2(wB.x), w3 = dup2(wB.y);
    a01 = fma2(w0, v0.x, a01); a23 = fma2(w0, v0.y, a23);
    a01 = fma2(w1, v1.x, a01); a23 = fma2(w1, v1.y, a23);
    a01 = fma2(w2, v2.x, a01); a23 = fma2(w2, v2.y, a23);
    a01 = fma2(w3, v3.x, a01); a23 = fma2(w3, v3.y, a23);
}

// ---------------- weight repack ----------------
__global__ void k_prep(const float* __restrict__ Wb0, const float* __restrict__ Wb1,
                       const float* __restrict__ Wff1, const float* __restrict__ Wff2,
                       const float* __restrict__ Wta, const float* __restrict__ Wtb,
                       const float* __restrict__ bff1, const float* __restrict__ bff2,
                       const float* __restrict__ bta, const float* __restrict__ btb) {
    int idx = blockIdx.x * blockDim.x + threadIdx.x;
    const int N0 = 35 * 256, N1 = 64 * 256, NH = 64 * 384;
    if (idx < N0) {
        int k4 = idx >> 8, u = idx & 255;
        float w[4];
#pragma unroll
        for (int j = 0; j < 4; j++) {
            int k = k4 * 4 + j;
            w[j] = (k < 140) ? Wb0[u * 140 + k] : 0.f;
        }
        g_W0q[idx] = pack4(w[0], w[1], w[2], w[3]);
    } else if (idx < N0 + N1) {
        int i = idx - N0;
        int k4 = i >> 8, u = i & 255;
        const float* p = Wb1 + u * 256 + k4 * 4;
        g_W1q[i] = pack4(p[0], p[1], p[2], p[3]);
    } else if (idx < N0 + N1 + NH) {
        int i = idx - N0 - N1;
        int k4 = i / 384, j = i % 384;
        float w[4];
#pragma unroll
        for (int jj = 0; jj < 4; jj++) {
            int k = k4 * 4 + jj;
            if (j < 128)       w[jj] = Wff1[j * 256 + k];
            else if (j < 256)  w[jj] = Wff2[(j - 128) * 256 + k];
            else               w[jj] = Wta[(j - 256) * 256 + k] + Wtb[(j - 256) * 256 + k];
        }
        g_Hq[i] = pack4(w[0], w[1], w[2], w[3]);
    } else if (idx < N0 + N1 + NH + 384) {
        int j = idx - N0 - N1 - NH;
        float b;
        if (j < 128)      b = bff1[j];
        else if (j < 256) b = bff2[j - 128];
        else              b = bta[j - 256] + btb[j - 256];
        g_bh[j] = b;
    }
}

// ---------------- collapsed _sff operators (stored transposed) ----------------
__device__ __forceinline__ float sff_contrib(const float* __restrict__ conv,
                                             const float* __restrict__ lin,
                                             int p, int seg, int pad, int so, int si) {
    int phase = so % p, q = so / p;
    float acc = 0.f;
    for (int kk = 0; kk < seg; ++kk) {
        int d = si - (kk * p + phase);
        float c = 0.f;
        if (d >= -pad && d <= pad) c = conv[d + pad];
        if (d == 0) c += 1.f;
        acc += lin[q * seg + kk] * c;
    }
    return acc;
}

__global__ void k_build_T(const float* __restrict__ c3, const float* __restrict__ l3,
                          const float* __restrict__ c6, const float* __restrict__ l6,
                          const float* __restrict__ c12, const float* __restrict__ l12,
                          const float* __restrict__ c24, const float* __restrict__ l24) {
    int idx = blockIdx.x * blockDim.x + threadIdx.x;
    if (idx >= 3 * S2_) return;
    int L = idx / S2_;
    int r = idx % S2_;
    int so = r / S_, si = r % S_;
    float a = sff_contrib(c3  + L * 3,  l3  + L * 56 * 56, 3, 56, 1, so, si)
            + sff_contrib(c6  + L * 7,  l6  + L * 28 * 28, 6, 28, 3, so, si)
            + sff_contrib(c12 + L * 13, l12 + L * 14 * 14, 12, 14, 6, so, si)
            + sff_contrib(c24 + L * 25, l24 + L * 7 * 7,  24, 7, 12, so, si);
    g_T[L * S2_ + si * S_ + so] = 0.25f * a;   // transposed store
}

__global__ void k_twf(const float* __restrict__ Wfits) {
    int idx = blockIdx.x * blockDim.x + threadIdx.x;
    if (idx >= 3 * S2_) return;
    int c = idx / S2_;
    int r = idx % S2_;
    int s = r / S_, p = r % S_;
    g_WfT[c * S2_ + s * S_ + p] = Wfits[c * S2_ + p * S_ + s];
}

// ---------------- per-(b,f) sequence mean ----------------
__global__ void k_mean(const float* __restrict__ x) {
    int w = (blockIdx.x * blockDim.x + threadIdx.x) >> 5;
    int lane = threadIdx.x & 31;
    if (w >= B_ * F_) return;
    const float* p = x + w * S_;
    float s = 0.f;
    for (int i = lane; i < S_; i += 32) s += p[i];
#pragma unroll
    for (int o = 16; o; o >>= 1) s += __shfl_xor_sync(0xffffffffu, s, o);
    if (!lane) g_mean[w] = s * (1.f / (float)S_);
}

// ---------------- fused front: x1 = T0@(xs-mean); x2 = T1@xin3; x3 = T2@xin3 ----
__global__ void k_front(const float* __restrict__ x) {
    __shared__ float xs[S_][F_];
    __shared__ float x1s[S_][4];
    int b = blockIdx.x, t = threadIdx.x;
    for (int i = t; i < S_ * F_; i += blockDim.x) {
        int si = i / F_, f = i % F_;
        xs[si][f] = x[b * F_ * S_ + f * S_ + si] - g_mean[b * F_ + f];
    }
    __syncthreads();
    if (t < S_) {
        float acc[F_];
#pragma unroll
        for (int f = 0; f < F_; f++) acc[f] = 0.f;
        for (int si = 0; si < S_; ++si) {
            float tw = g_T[si * S_ + t];          // coalesced
#pragma unroll
            for (int f = 0; f < F_; f++) acc[f] = fmaf(tw, xs[si][f], acc[f]);
        }
        float* o = g_x1 + (b * S_ + t) * F_;
#pragma unroll
        for (int f = 0; f < F_; f++) o[f] = acc[f];
        x1s[t][0] = acc[0]; x1s[t][1] = acc[1]; x1s[t][2] = acc[2];
    }
    __syncthreads();
    if (t < S_) {
        float a2[3] = {0.f, 0.f, 0.f};
        float a3[3] = {0.f, 0.f, 0.f};
        for (int si = 0; si < S_; ++si) {
            float t1 = g_T[S2_ + si * S_ + t];
            float t2 = g_T[2 * S2_ + si * S_ + t];
#pragma unroll
            for (int c = 0; c < 3; c++) {
                a2[c] = fmaf(t1, x1s[si][c], a2[c]);
                a3[c] = fmaf(t2, x1s[si][c], a3[c]);
            }
        }
#pragma unroll
        for (int c = 0; c < 3; c++) {
            g_x2[(b * S_ + t) * 3 + c] = a2[c];
            g_x3[(b * S_ + t) * 3 + c] = a3[c];
        }
    }
}

// ---------------- CfC recurrence: 128 CTAs x 4 rows, f32x2 math ----------------
__global__ void __launch_bounds__(256, 1) k_rnn(const float* __restrict__ bb0,
                                                const float* __restrict__ bb1) {
    extern __shared__ __align__(16) char sraw[];
    uint2* sW0  = reinterpret_cast<uint2*>(sraw);            // 35*256
    uint2* sW1  = sW0 + 35 * 256;                            // 64*256
    float4* inx = reinterpret_cast<float4*>(sW1 + 64 * 256); // [2][12]
    float4* inh = inx + 24;                                  // [128]
    float4* za  = inh + 128;                                 // [256]
    float4* zb  = za + 256;                                  // [256]
    float4* hd  = zb + 256;                                  // [384]

    const int t = threadIdx.x;
    const int bb = blockIdx.x * NB;

    // one-time weight staging into SMEM
    {
        const uint4* s0 = reinterpret_cast<const uint4*>(g_W0q);
        uint4* d0 = reinterpret_cast<uint4*>(sW0);
        for (int i = t; i < 35 * 128; i += 256) d0[i] = s0[i];
        const uint4* s1 = reinterpret_cast<const uint4*>(g_W1q);
        uint4* d1 = reinterpret_cast<uint4*>(sW1);
        for (int i = t; i < 64 * 128; i += 256) d1[i] = s1[i];
    }

    const float rb0 = bb0[t], rb1 = bb1[t];
    const float rh1 = g_bh[t];
    const float rh2 = (t < 128) ? g_bh[256 + t] : 0.f;

    if (t < 128) inh[t] = make_float4(0.f, 0.f, 0.f, 0.f);
    if (t < 48) {
        int r = t / 12, f = t - r * 12;
        reinterpret_cast<float*>(&inx[f])[r] = g_x1[(bb + r) * S_ * F_ + f];
    }

    for (int step = 0; step < S_; ++step) {
        const int par = step & 1;
        __syncthreads();   // B1: inh/inx visible

        // ---- layer 0: 140 -> 256, silu ----
        u64 a01 = dup2(rb0), a23 = dup2(rb0);
        {
            const float4* xx = inx + par * 12;
#pragma unroll
            for (int k4 = 0; k4 < 3; k4++) {
                uint2 wv = sW0[k4 * 256 + t];
                MAC4(wv, reinterpret_cast<const ulonglong2*>(xx + k4 * 4), a01, a23);
            }
#pragma unroll 8
            for (int k4 = 3; k4 < 35; k4++) {
                uint2 wv = sW0[k4 * 256 + t];
                MAC4(wv, reinterpret_cast<const ulonglong2*>(inh + (k4 * 4 - 12)), a01, a23);
            }
        }
        {
            float2 p = unp(a01), q = unp(a23);
            za[t] = make_float4(siluf(p.x), siluf(p.y), siluf(q.x), siluf(q.y));
        }
        __syncthreads();   // B2

        // ---- layer 1: 256 -> 256, silu ----
        a01 = dup2(rb1); a23 = dup2(rb1);
#pragma unroll 8
        for (int k4 = 0; k4 < 64; k4++) {
            uint2 wv = sW1[k4 * 256 + t];
            MAC4(wv, reinterpret_cast<const ulonglong2*>(za + k4 * 4), a01, a23);
        }
        {
            float2 p = unp(a01), q = unp(a23);
            zb[t] = make_float4(siluf(p.x), siluf(p.y), siluf(q.x), siluf(q.y));
        }
        __syncthreads();   // B3

        // ---- head: 256 -> 384 streamed from L2; prefetch next x ----
        float xpre = 0.f;
        if (t < 48) {
            int r = t / 12, f = t - r * 12;
            int ns = (step + 1 < S_) ? step + 1 : step;
            xpre = __ldg(&g_x1[((bb + r) * S_ + ns) * F_ + f]);
        }
        a01 = dup2(rh1); a23 = dup2(rh1);
        if (t < 128) {
            u64 b01 = dup2(rh2), b23 = dup2(rh2);
            uint2 wa[4], wb[4];
#pragma unroll
            for (int j = 0; j < 4; j++) {
                wa[j] = g_Hq[j * 384 + t];
                wb[j] = g_Hq[j * 384 + 256 + t];
            }
#pragma unroll 4
            for (int k4 = 0; k4 < 64; k4++) {
                uint2 w1 = wa[k4 & 3], w2 = wb[k4 & 3];
                if (k4 < 60) {
                    wa[k4 & 3] = g_Hq[(k4 + 4) * 384 + t];
                    wb[k4 & 3] = g_Hq[(k4 + 4) * 384 + 256 + t];
                }
                const ulonglong2* acts = reinterpret_cast<const ulonglong2*>(zb + k4 * 4);
                ulonglong2 v0 = acts[0], v1 = acts[1], v2 = acts[2], v3 = acts[3];
                MAC4v(w1, v0, v1, v2, v3, a01, a23);
                MAC4v(w2, v0, v1, v2, v3, b01, b23);
            }
            float2 p = unp(b01), q = unp(b23);
            hd[256 + t] = make_float4(p.x, p.y, q.x, q.y);
        } else {
            uint2 wa[8];
#pragma unroll
            for (int j = 0; j < 8; j++) wa[j] = g_Hq[j * 384 + t];
#pragma unroll 8
            for (int k4 = 0; k4 < 64; k4++) {
                uint2 w1 = wa[k4 & 7];
                if (k4 < 56) wa[k4 & 7] = g_Hq[(k4 + 8) * 384 + t];
                MAC4(w1, reinterpret_cast<const ulonglong2*>(zb + k4 * 4), a01, a23);
            }
        }
        {
            float2 p = unp(a01), q = unp(a23);
            hd[t] = make_float4(p.x, p.y, q.x, q.y);
        }
        if (t < 48) {
            int r = t / 12, f = t - r * 12;
            reinterpret_cast<float*>(&inx[(par ^ 1) * 12 + f])[r] = xpre;
        }
        __syncthreads();   // B4

        // ---- combine + feedback + store h ----
        if (t < 128) {
            float4 v1 = hd[t], v2 = hd[128 + t], vg = hd[256 + t];
            float h0, h1, h2, h3;
            {
                float f1 = tanhf_fast(v1.x), f2 = tanhf_fast(v2.x), s = sigf(vg.x);
                h0 = f1 + s * (f2 - f1);
            }
            {
                float f1 = tanhf_fast(v1.y), f2 = tanhf_fast(v2.y), s = sigf(vg.y);
                h1 = f1 + s * (f2 - f1);
            }
            {
                float f1 = tanhf_fast(v1.z), f2 = tanhf_fast(v2.z), s = sigf(vg.z);
                h2 = f1 + s * (f2 - f1);
            }
            {
                float f1 = tanhf_fast(v1.w), f2 = tanhf_fast(v2.w), s = sigf(vg.w);
                h3 = f1 + s * (f2 - f1);
            }
            inh[t] = make_float4(h0, h1, h2, h3);
            g_hs[((bb + 0) * S_ + step) * H_ + t] = h0;
            g_hs[((bb + 1) * S_ + step) * H_ + t] = h1;
            g_hs[((bb + 2) * S_ + step) * H_ + t] = h2;
            g_hs[((bb + 3) * S_ + step) * H_ + t] = h3;
        }
    }
}

// ---------------- fused back: readout + fits + residuals ----------------
__global__ void k_back(const float* __restrict__ Wfc, const float* __restrict__ bfc,
                       float* __restrict__ out) {
    __shared__ float r1s[S_][4];
    int b = blockIdx.x, t = threadIdx.x;
    int w = t >> 5, lane = t & 31;
    for (int s = w; s < S_; s += 8) {
        const float* h = g_hs + (size_t)(b * S_ + s) * H_;
        float a0 = 0.f, a1 = 0.f, a2 = 0.f;
        for (int i = lane; i < H_; i += 32) {
            float hv = h[i];
            a0 = fmaf(hv, Wfc[i], a0);
            a1 = fmaf(hv, Wfc[H_ + i], a1);
            a2 = fmaf(hv, Wfc[2 * H_ + i], a2);
        }
#pragma unroll
        for (int o = 16; o; o >>= 1) {
            a0 += __shfl_xor_sync(0xffffffffu, a0, o);
            a1 += __shfl_xor_sync(0xffffffffu, a1, o);
            a2 += __shfl_xor_sync(0xffffffffu, a2, o);
        }
        if (!lane) {
            r1s[s][0] = a0 + bfc[0] + g_x3[(b * S_ + s) * 3 + 0];
            r1s[s][1] = a1 + bfc[1] + g_x3[(b * S_ + s) * 3 + 1];
            r1s[s][2] = a2 + bfc[2] + g_x3[(b * S_ + s) * 3 + 2];
        }
    }
    __syncthreads();
    if (t < S_) {
        float a0 = g_mean[b * F_ + 0] + g_x2[(b * S_ + t) * 3 + 0];
        float a1 = g_mean[b * F_ + 1] + g_x2[(b * S_ + t) * 3 + 1];
        float a2 = g_mean[b * F_ + 2] + g_x2[(b * S_ + t) * 3 + 2];
        for (int s = 0; s < S_; ++s) {
            a0 = fmaf(r1s[s][0], g_WfT[0 * S2_ + s * S_ + t], a0);
            a1 = fmaf(r1s[s][1], g_WfT[1 * S2_ + s * S_ + t], a1);
            a2 = fmaf(r1s[s][2], g_WfT[2 * S2_ + s * S_ + t], a2);
        }
        float* o = out + (b * S_ + t) * 3;
        o[0] = a0; o[1] = a1; o[2] = a2;
    }
}

// ---------------- launch ----------------
extern "C" void kernel_launch(void* const* d_in, const int* in_sizes, int n_in,
                              void* d_out, int out_size) {
    const float* x     = (const float*)d_in[0];
    const float* c3    = (const float*)d_in[1];
    const float* l3    = (const float*)d_in[2];
    const float* c6    = (const float*)d_in[3];
    const float* l6    = (const float*)d_in[4];
    const float* c12   = (const float*)d_in[5];
    const float* l12   = (const float*)d_in[6];
    const float* c24   = (const float*)d_in[7];
    const float* l24   = (const float*)d_in[8];
    const float* Wb0   = (const float*)d_in[9];
    const float* bb0   = (const float*)d_in[10];
    const float* Wb1   = (const float*)d_in[11];
    const float* bb1   = (const float*)d_in[12];
    const float* Wff1  = (const float*)d_in[13];
    const float* bff1  = (const float*)d_in[14];
    const float* Wff2  = (const float*)d_in[15];
    const float* bff2  = (const float*)d_in[16];
    const float* Wta   = (const float*)d_in[17];
    const float* bta   = (const float*)d_in[18];
    const float* Wtb   = (const float*)d_in[19];
    const float* btb   = (const float*)d_in[20];
    const float* Wfc   = (const float*)d_in[21];
    const float* bfc   = (const float*)d_in[22];
    const float* Wfits = (const float*)d_in[23];
    float* out = (float*)d_out;

    const int SMEM_RNN = (35 * 256 + 64 * 256) * 8 + (24 + 128 + 256 + 256 + 384) * 16;
    static int smem_set = 0;
    if (!smem_set) {
        cudaFuncSetAttribute(k_rnn, cudaFuncAttributeMaxDynamicSharedMemorySize, SMEM_RNN);
        smem_set = 1;
    }

    k_prep<<<(50304 + 255) / 256, 256>>>(Wb0, Wb1, Wff1, Wff2, Wta, Wtb,
                                         bff1, bff2, bta, btb);
    k_build_T<<<(3 * S2_ + 255) / 256, 256>>>(c3, l3, c6, l6, c12, l12, c24, l24);
    k_twf<<<(3 * S2_ + 255) / 256, 256>>>(Wfits);
    k_mean<<<(B_ * F_ * 32 + 255) / 256, 256>>>(x);
    k_front<<<B_, 192>>>(x);
    k_rnn<<<B_ / NB, 256, SMEM_RNN>>>(bb0, bb1);
    k_back<<<B_, 256>>>(Wfc, bfc, out);
}

// round 5
// speedup vs baseline: 1.4340x; 1.0009x over previous
#include <cuda_runtime.h>
#include <cuda_fp16.h>

#define B_ 512
#define S_ 168
#define F_ 12
#define H_ 128
#define U_ 256
#define O_ 3
#define NB 4
#define S2_ (S_ * S_)

typedef unsigned long long u64;

// ---------------- device scratch ----------------
__device__ uint2 g_W0q[35 * 256];     // layer0 [k4][u]
__device__ uint2 g_W1q[64 * 256];     // layer1 [k4][u]
__device__ uint2 g_Hq[64 * 384];      // merged head [k4][j]
__device__ float g_bh[384];
__device__ float g_T[3 * S2_];        // TRANSPOSED: [L][si][so]
__device__ float g_WfT[3 * S2_];      // TRANSPOSED: [c][s][p]
__device__ float g_mean[B_ * F_];
__device__ float g_x1[B_ * S_ * F_];
__device__ float g_x2[B_ * S_ * O_];
__device__ float g_x3[B_ * S_ * O_];
__device__ float g_hs[B_ * S_ * H_];

// ---------------- f32x2 helpers ----------------
__device__ __forceinline__ u64 dup2(float w) {
    u64 r;
    asm("mov.b64 %0, {%1, %2};" : "=l"(r) : "f"(w), "f"(w));
    return r;
}
__device__ __forceinline__ u64 fma2(u64 a, u64 b, u64 c) {
    u64 d;
    asm("fma.rn.f32x2 %0, %1, %2, %3;" : "=l"(d) : "l"(a), "l"(b), "l"(c));
    return d;
}
__device__ __forceinline__ float2 unp(u64 v) {
    float2 f;
    asm("mov.b64 {%0, %1}, %2;" : "=f"(f.x), "=f"(f.y) : "l"(v));
    return f;
}

__device__ __forceinline__ float siluf(float x) {
    return __fdividef(x, 1.f + __expf(-x));
}
__device__ __forceinline__ float sigf(float x) {
    return __fdividef(1.f, 1.f + __expf(-x));
}
__device__ __forceinline__ float tanhf_fast(float x) {
    float e = __expf(2.f * x);
    return 1.f - __fdividef(2.f, e + 1.f);
}

__device__ __forceinline__ uint2 pack4(float a, float b, float c, float d) {
    __half2 lo = __halves2half2(__float2half_rn(a), __float2half_rn(b));
    __half2 hi = __halves2half2(__float2half_rn(c), __float2half_rn(d));
    uint2 r;
    r.x = *reinterpret_cast<unsigned*>(&lo);
    r.y = *reinterpret_cast<unsigned*>(&hi);
    return r;
}

// one weight uint2 (4 k), acts = 4 float4 (rows packed per k)
__device__ __forceinline__ void MAC4(uint2 wv, const ulonglong2* __restrict__ acts,
                                     u64& a01, u64& a23) {
    float2 wA = __half22float2(*reinterpret_cast<const __half2*>(&wv.x));
    float2 wB = __half22float2(*reinterpret_cast<const __half2*>(&wv.y));
    u64 w0 = dup2(wA.x), w1 = dup2(wA.y), w2 = dup2(wB.x), w3 = dup2(wB.y);
    ulonglong2 v0 = acts[0], v1 = acts[1], v2 = acts[2], v3 = acts[3];
    a01 = fma2(w0, v0.x, a01); a23 = fma2(w0, v0.y, a23);
    a01 = fma2(w1, v1.x, a01); a23 = fma2(w1, v1.y, a23);
    a01 = fma2(w2, v2.x, a01); a23 = fma2(w2, v2.y, a23);
    a01 = fma2(w3, v3.x, a01); a23 = fma2(w3, v3.y, a23);
}
__device__ __forceinline__ void MAC4v(uint2 wv, ulonglong2 v0, ulonglong2 v1,
                                      ulonglong2 v2, ulonglong2 v3,
                                      u64& a01, u64& a23) {
    float2 wA = __half22float2(*reinterpret_cast<const __half2*>(&wv.x));
    float2 wB = __half22float2(*reinterpret_cast<const __half2*>(&wv.y));
    u64 w0 = dup2(wA.x), w1 = dup2(wA.y), w2 = dup2(wB.x), w3 = dup2(wB.y);
    a01 = fma2(w0, v0.x, a01); a23 = fma2(w0, v0.y, a23);
    a01 = fma2(w1, v1.x, a01); a23 = fma2(w1, v1.y, a23);
    a01 = fma2(w2, v2.x, a01); a23 = fma2(w2, v2.y, a23);
    a01 = fma2(w3, v3.x, a01); a23 = fma2(w3, v3.y, a23);
}

// ---------------- weight repack ----------------
__global__ void k_prep(const float* __restrict__ Wb0, const float* __restrict__ Wb1,
                       const float* __restrict__ Wff1, const float* __restrict__ Wff2,
                       const float* __restrict__ Wta, const float* __restrict__ Wtb,
                       const float* __restrict__ bff1, const float* __restrict__ bff2,
                       const float* __restrict__ bta, const float* __restrict__ btb) {
    int idx = blockIdx.x * blockDim.x + threadIdx.x;
    const int N0 = 35 * 256, N1 = 64 * 256, NH = 64 * 384;
    if (idx < N0) {
        int k4 = idx >> 8, u = idx & 255;
        float w[4];
#pragma unroll
        for (int j = 0; j < 4; j++) {
            int k = k4 * 4 + j;
            w[j] = (k < 140) ? Wb0[u * 140 + k] : 0.f;
        }
        g_W0q[idx] = pack4(w[0], w[1], w[2], w[3]);
    } else if (idx < N0 + N1) {
        int i = idx - N0;
        int k4 = i >> 8, u = i & 255;
        const float* p = Wb1 + u * 256 + k4 * 4;
        g_W1q[i] = pack4(p[0], p[1], p[2], p[3]);
    } else if (idx < N0 + N1 + NH) {
        int i = idx - N0 - N1;
        int k4 = i / 384, j = i % 384;
        float w[4];
#pragma unroll
        for (int jj = 0; jj < 4; jj++) {
            int k = k4 * 4 + jj;
            if (j < 128)       w[jj] = Wff1[j * 256 + k];
            else if (j < 256)  w[jj] = Wff2[(j - 128) * 256 + k];
            else               w[jj] = Wta[(j - 256) * 256 + k] + Wtb[(j - 256) * 256 + k];
        }
        g_Hq[i] = pack4(w[0], w[1], w[2], w[3]);
    } else if (idx < N0 + N1 + NH + 384) {
        int j = idx - N0 - N1 - NH;
        float b;
        if (j < 128)      b = bff1[j];
        else if (j < 256) b = bff2[j - 128];
        else              b = bta[j - 256] + btb[j - 256];
        g_bh[j] = b;
    }
}

// ---------------- collapsed _sff operators (stored transposed) ----------------
__device__ __forceinline__ float sff_contrib(const float* __restrict__ conv,
                                             const float* __restrict__ lin,
                                             int p, int seg, int pad, int so, int si) {
    int phase = so % p, q = so / p;
    float acc = 0.f;
    for (int kk = 0; kk < seg; ++kk) {
        int d = si - (kk * p + phase);
        float c = 0.f;
        if (d >= -pad && d <= pad) c = conv[d + pad];
        if (d == 0) c += 1.f;
        acc += lin[q * seg + kk] * c;
    }
    return acc;
}

__global__ void k_build_T(const float* __restrict__ c3, const float* __restrict__ l3,
                          const float* __restrict__ c6, const float* __restrict__ l6,
                          const float* __restrict__ c12, const float* __restrict__ l12,
                          const float* __restrict__ c24, const float* __restrict__ l24) {
    int idx = blockIdx.x * blockDim.x + threadIdx.x;
    if (idx >= 3 * S2_) return;
    int L = idx / S2_;
    int r = idx % S2_;
    int so = r / S_, si = r % S_;
    float a = sff_contrib(c3  + L * 3,  l3  + L * 56 * 56, 3, 56, 1, so, si)
            + sff_contrib(c6  + L * 7,  l6  + L * 28 * 28, 6, 28, 3, so, si)
            + sff_contrib(c12 + L * 13, l12 + L * 14 * 14, 12, 14, 6, so, si)
            + sff_contrib(c24 + L * 25, l24 + L * 7 * 7,  24, 7, 12, so, si);
    g_T[L * S2_ + si * S_ + so] = 0.25f * a;   // transposed store
}

__global__ void k_twf(const float* __restrict__ Wfits) {
    int idx = blockIdx.x * blockDim.x + threadIdx.x;
    if (idx >= 3 * S2_) return;
    int c = idx / S2_;
    int r = idx % S2_;
    int s = r / S_, p = r % S_;
    g_WfT[c * S2_ + s * S_ + p] = Wfits[c * S2_ + p * S_ + s];
}

// ---------------- per-(b,f) sequence mean ----------------
__global__ void k_mean(const float* __restrict__ x) {
    int w = (blockIdx.x * blockDim.x + threadIdx.x) >> 5;
    int lane = threadIdx.x & 31;
    if (w >= B_ * F_) return;
    const float* p = x + w * S_;
    float s = 0.f;
    for (int i = lane; i < S_; i += 32) s += p[i];
#pragma unroll
    for (int o = 16; o; o >>= 1) s += __shfl_xor_sync(0xffffffffu, s, o);
    if (!lane) g_mean[w] = s * (1.f / (float)S_);
}

// ---------------- fused front: x1 = T0@(xs-mean); x2 = T1@xin3; x3 = T2@xin3 ----
__global__ void k_front(const float* __restrict__ x) {
    __shared__ float xs[S_][F_];
    __shared__ float x1s[S_][4];
    int b = blockIdx.x, t = threadIdx.x;
    for (int i = t; i < S_ * F_; i += blockDim.x) {
        int si = i / F_, f = i % F_;
        xs[si][f] = x[b * F_ * S_ + f * S_ + si] - g_mean[b * F_ + f];
    }
    __syncthreads();
    if (t < S_) {
        float acc[F_];
#pragma unroll
        for (int f = 0; f < F_; f++) acc[f] = 0.f;
        for (int si = 0; si < S_; ++si) {
            float tw = g_T[si * S_ + t];          // coalesced
#pragma unroll
            for (int f = 0; f < F_; f++) acc[f] = fmaf(tw, xs[si][f], acc[f]);
        }
        float* o = g_x1 + (b * S_ + t) * F_;
#pragma unroll
        for (int f = 0; f < F_; f++) o[f] = acc[f];
        x1s[t][0] = acc[0]; x1s[t][1] = acc[1]; x1s[t][2] = acc[2];
    }
    __syncthreads();
    if (t < S_) {
        float a2[3] = {0.f, 0.f, 0.f};
        float a3[3] = {0.f, 0.f, 0.f};
        for (int si = 0; si < S_; ++si) {
            float t1 = g_T[S2_ + si * S_ + t];
            float t2 = g_T[2 * S2_ + si * S_ + t];
#pragma unroll
            for (int c = 0; c < 3; c++) {
                a2[c] = fmaf(t1, x1s[si][c], a2[c]);
                a3[c] = fmaf(t2, x1s[si][c], a3[c]);
            }
        }
#pragma unroll
        for (int c = 0; c < 3; c++) {
            g_x2[(b * S_ + t) * 3 + c] = a2[c];
            g_x3[(b * S_ + t) * 3 + c] = a3[c];
        }
    }
}

// ---------------- CfC recurrence: 128 CTAs x 4 rows, f32x2 math ----------------
__global__ void __launch_bounds__(256, 1) k_rnn(const float* __restrict__ bb0,
                                                const float* __restrict__ bb1) {
    extern __shared__ __align__(16) char sraw[];
    uint2* sW0  = reinterpret_cast<uint2*>(sraw);            // 35*256
    uint2* sW1  = sW0 + 35 * 256;                            // 64*256
    float4* inx = reinterpret_cast<float4*>(sW1 + 64 * 256); // [2][12]
    float4* inh = inx + 24;                                  // [128]
    float4* za  = inh + 128;                                 // [256]
    float4* zb  = za + 256;                                  // [256]
    float4* hd  = zb + 256;                                  // [384]

    const int t = threadIdx.x;
    const int bb = blockIdx.x * NB;

    // one-time weight staging into SMEM
    {
        const uint4* s0 = reinterpret_cast<const uint4*>(g_W0q);
        uint4* d0 = reinterpret_cast<uint4*>(sW0);
        for (int i = t; i < 35 * 128; i += 256) d0[i] = s0[i];
        const uint4* s1 = reinterpret_cast<const uint4*>(g_W1q);
        uint4* d1 = reinterpret_cast<uint4*>(sW1);
        for (int i = t; i < 64 * 128; i += 256) d1[i] = s1[i];
    }

    const float rb0 = bb0[t], rb1 = bb1[t];
    const float rh1 = g_bh[t];
    const float rh2 = (t < 128) ? g_bh[256 + t] : 0.f;

    if (t < 128) inh[t] = make_float4(0.f, 0.f, 0.f, 0.f);
    if (t < 48) {
        int r = t / 12, f = t - r * 12;
        reinterpret_cast<float*>(&inx[f])[r] = g_x1[(bb + r) * S_ * F_ + f];
    }

    for (int step = 0; step < S_; ++step) {
        const int par = step & 1;
        __syncthreads();   // B1: inh/inx visible

        // ---- layer 0: 140 -> 256, silu ----
        u64 a01 = dup2(rb0), a23 = dup2(rb0);
        {
            const float4* xx = inx + par * 12;
#pragma unroll
            for (int k4 = 0; k4 < 3; k4++) {
                uint2 wv = sW0[k4 * 256 + t];
                MAC4(wv, reinterpret_cast<const ulonglong2*>(xx + k4 * 4), a01, a23);
            }
#pragma unroll 8
            for (int k4 = 3; k4 < 35; k4++) {
                uint2 wv = sW0[k4 * 256 + t];
                MAC4(wv, reinterpret_cast<const ulonglong2*>(inh + (k4 * 4 - 12)), a01, a23);
            }
        }
        {
            float2 p = unp(a01), q = unp(a23);
            za[t] = make_float4(siluf(p.x), siluf(p.y), siluf(q.x), siluf(q.y));
        }
        __syncthreads();   // B2

        // ---- layer 1: 256 -> 256, silu ----
        a01 = dup2(rb1); a23 = dup2(rb1);
#pragma unroll 8
        for (int k4 = 0; k4 < 64; k4++) {
            uint2 wv = sW1[k4 * 256 + t];
            MAC4(wv, reinterpret_cast<const ulonglong2*>(za + k4 * 4), a01, a23);
        }
        {
            float2 p = unp(a01), q = unp(a23);
            zb[t] = make_float4(siluf(p.x), siluf(p.y), siluf(q.x), siluf(q.y));
        }
        __syncthreads();   // B3

        // ---- head: 256 -> 384 streamed from L2; prefetch next x ----
        float xpre = 0.f;
        if (t < 48) {
            int r = t / 12, f = t - r * 12;
            int ns = (step + 1 < S_) ? step + 1 : step;
            xpre = __ldg(&g_x1[((bb + r) * S_ + ns) * F_ + f]);
        }
        a01 = dup2(rh1); a23 = dup2(rh1);
        if (t < 128) {
            u64 b01 = dup2(rh2), b23 = dup2(rh2);
            uint2 wa[4], wb[4];
#pragma unroll
            for (int j = 0; j < 4; j++) {
                wa[j] = g_Hq[j * 384 + t];
                wb[j] = g_Hq[j * 384 + 256 + t];
            }
#pragma unroll 4
            for (int k4 = 0; k4 < 64; k4++) {
                uint2 w1 = wa[k4 & 3], w2 = wb[k4 & 3];
                if (k4 < 60) {
                    wa[k4 & 3] = g_Hq[(k4 + 4) * 384 + t];
                    wb[k4 & 3] = g_Hq[(k4 + 4) * 384 + 256 + t];
                }
                const ulonglong2* acts = reinterpret_cast<const ulonglong2*>(zb + k4 * 4);
                ulonglong2 v0 = acts[0], v1 = acts[1], v2 = acts[2], v3 = acts[3];
                MAC4v(w1, v0, v1, v2, v3, a01, a23);
                MAC4v(w2, v0, v1, v2, v3, b01, b23);
            }
            float2 p = unp(b01), q = unp(b23);
            hd[256 + t] = make_float4(p.x, p.y, q.x, q.y);
        } else {
            uint2 wa[8];
#pragma unroll
            for (int j = 0; j < 8; j++) wa[j] = g_Hq[j * 384 + t];
#pragma unroll 8
            for (int k4 = 0; k4 < 64; k4++) {
                uint2 w1 = wa[k4 & 7];
                if (k4 < 56) wa[k4 & 7] = g_Hq[(k4 + 8) * 384 + t];
                MAC4(w1, reinterpret_cast<const ulonglong2*>(zb + k4 * 4), a01, a23);
            }
        }
        {
            float2 p = unp(a01), q = unp(a23);
            hd[t] = make_float4(p.x, p.y, q.x, q.y);
        }
        if (t < 48) {
            int r = t / 12, f = t - r * 12;
            reinterpret_cast<float*>(&inx[(par ^ 1) * 12 + f])[r] = xpre;
        }
        __syncthreads();   // B4

        // ---- combine + feedback + store h ----
        if (t < 128) {
            float4 v1 = hd[t], v2 = hd[128 + t], vg = hd[256 + t];
            float h0, h1, h2, h3;
            {
                float f1 = tanhf_fast(v1.x), f2 = tanhf_fast(v2.x), s = sigf(vg.x);
                h0 = f1 + s * (f2 - f1);
            }
            {
                float f1 = tanhf_fast(v1.y), f2 = tanhf_fast(v2.y), s = sigf(vg.y);
                h1 = f1 + s * (f2 - f1);
            }
            {
                float f1 = tanhf_fast(v1.z), f2 = tanhf_fast(v2.z), s = sigf(vg.z);
                h2 = f1 + s * (f2 - f1);
            }
            {
                float f1 = tanhf_fast(v1.w), f2 = tanhf_fast(v2.w), s = sigf(vg.w);
                h3 = f1 + s * (f2 - f1);
            }
            inh[t] = make_float4(h0, h1, h2, h3);
            g_hs[((bb + 0) * S_ + step) * H_ + t] = h0;
            g_hs[((bb + 1) * S_ + step) * H_ + t] = h1;
            g_hs[((bb + 2) * S_ + step) * H_ + t] = h2;
            g_hs[((bb + 3) * S_ + step) * H_ + t] = h3;
        }
    }
}

// ---------------- fused back: readout + fits + residuals ----------------
__global__ void k_back(const float* __restrict__ Wfc, const float* __restrict__ bfc,
                       float* __restrict__ out) {
    __shared__ float r1s[S_][4];
    int b = blockIdx.x, t = threadIdx.x;
    int w = t >> 5, lane = t & 31;
    for (int s = w; s < S_; s += 8) {
        const float* h = g_hs + (size_t)(b * S_ + s) * H_;
        float a0 = 0.f, a1 = 0.f, a2 = 0.f;
        for (int i = lane; i < H_; i += 32) {
            float hv = h[i];
            a0 = fmaf(hv, Wfc[i], a0);
            a1 = fmaf(hv, Wfc[H_ + i], a1);
            a2 = fmaf(hv, Wfc[2 * H_ + i], a2);
        }
#pragma unroll
        for (int o = 16; o; o >>= 1) {
            a0 += __shfl_xor_sync(0xffffffffu, a0, o);
            a1 += __shfl_xor_sync(0xffffffffu, a1, o);
            a2 += __shfl_xor_sync(0xffffffffu, a2, o);
        }
        if (!lane) {
            r1s[s][0] = a0 + bfc[0] + g_x3[(b * S_ + s) * 3 + 0];
            r1s[s][1] = a1 + bfc[1] + g_x3[(b * S_ + s) * 3 + 1];
            r1s[s][2] = a2 + bfc[2] + g_x3[(b * S_ + s) * 3 + 2];
        }
    }
    __syncthreads();
    if (t < S_) {
        float a0 = g_mean[b * F_ + 0] + g_x2[(b * S_ + t) * 3 + 0];
        float a1 = g_mean[b * F_ + 1] + g_x2[(b * S_ + t) * 3 + 1];
        float a2 = g_mean[b * F_ + 2] + g_x2[(b * S_ + t) * 3 + 2];
        for (int s = 0; s < S_; ++s) {
            a0 = fmaf(r1s[s][0], g_WfT[0 * S2_ + s * S_ + t], a0);
            a1 = fmaf(r1s[s][1], g_WfT[1 * S2_ + s * S_ + t], a1);
            a2 = fmaf(r1s[s][2], g_WfT[2 * S2_ + s * S_ + t], a2);
        }
        float* o = out + (b * S_ + t) * 3;
        o[0] = a0; o[1] = a1; o[2] = a2;
    }
}

// ---------------- launch ----------------
extern "C" void kernel_launch(void* const* d_in, const int* in_sizes, int n_in,
                              void* d_out, int out_size) {
    const float* x     = (const float*)d_in[0];
    const float* c3    = (const float*)d_in[1];
    const float* l3    = (const float*)d_in[2];
    const float* c6    = (const float*)d_in[3];
    const float* l6    = (const float*)d_in[4];
    const float* c12   = (const float*)d_in[5];
    const float* l12   = (const float*)d_in[6];
    const float* c24   = (const float*)d_in[7];
    const float* l24   = (const float*)d_in[8];
    const float* Wb0   = (const float*)d_in[9];
    const float* bb0   = (const float*)d_in[10];
    const float* Wb1   = (const float*)d_in[11];
    const float* bb1   = (const float*)d_in[12];
    const float* Wff1  = (const float*)d_in[13];
    const float* bff1  = (const float*)d_in[14];
    const float* Wff2  = (const float*)d_in[15];
    const float* bff2  = (const float*)d_in[16];
    const float* Wta   = (const float*)d_in[17];
    const float* bta   = (const float*)d_in[18];
    const float* Wtb   = (const float*)d_in[19];
    const float* btb   = (const float*)d_in[20];
    const float* Wfc   = (const float*)d_in[21];
    const float* bfc   = (const float*)d_in[22];
    const float* Wfits = (const float*)d_in[23];
    float* out = (float*)d_out;

    const int SMEM_RNN = (35 * 256 + 64 * 256) * 8 + (24 + 128 + 256 + 256 + 384) * 16;
    static int smem_set = 0;
    if (!smem_set) {
        cudaFuncSetAttribute(k_rnn, cudaFuncAttributeMaxDynamicSharedMemorySize, SMEM_RNN);
        smem_set = 1;
    }

    k_prep<<<(50304 + 255) / 256, 256>>>(Wb0, Wb1, Wff1, Wff2, Wta, Wtb,
                                         bff1, bff2, bta, btb);
    k_build_T<<<(3 * S2_ + 255) / 256, 256>>>(c3, l3, c6, l6, c12, l12, c24, l24);
    k_twf<<<(3 * S2_ + 255) / 256, 256>>>(Wfits);
    k_mean<<<(B_ * F_ * 32 + 255) / 256, 256>>>(x);
    k_front<<<B_, 192>>>(x);
    k_rnn<<<B_ / NB, 256, SMEM_RNN>>>(bb0, bb1);
    k_back<<<B_, 256>>>(Wfc, bfc, out);
}

// round 6
// speedup vs baseline: 3.1234x; 2.1781x over previous
#include <cuda_runtime.h>
#include <cuda_fp16.h>

#define B_ 512
#define S_ 168
#define F_ 12
#define H_ 128
#define O_ 3
#define S2_ (S_ * S_)
#define ROWS 8            // batch rows per CTA
#define NCTA (B_ / ROWS)  // 64

typedef unsigned int u32;

// ---------------- device scratch ----------------
__device__ uint4 g_W0f[16 * 9 * 32];    // L0 fragments [tile][kstep][lane]
__device__ uint4 g_W1f[16 * 16 * 32];   // L1 fragments
__device__ uint4 g_Hf[24 * 16 * 32];    // head fragments
__device__ float g_bh[384];             // merged head bias
__device__ float g_T[3 * S2_];          // transposed [L][si][so]
__device__ float g_WfT[3 * S2_];        // transposed [c][s][p]
__device__ float g_mean[B_ * F_];
__device__ float g_x1[B_ * S_ * F_];
__device__ float g_x2[B_ * S_ * O_];
__device__ float g_x3[B_ * S_ * O_];
__device__ float g_hs[B_ * S_ * H_];

// ---------------- helpers ----------------
__device__ __forceinline__ float siluf(float x) { return __fdividef(x, 1.f + __expf(-x)); }
__device__ __forceinline__ float sigf(float x)  { return __fdividef(1.f, 1.f + __expf(-x)); }
__device__ __forceinline__ float tanhf_fast(float x) {
    float e = __expf(2.f * x);
    return 1.f - __fdividef(2.f, e + 1.f);
}
__device__ __forceinline__ u32 hpack(float a, float b) {
    __half2 h = __floats2half2_rn(a, b);
    return *reinterpret_cast<u32*>(&h);
}
__device__ __forceinline__ void mma16816(float* d, uint4 A, u32 b0, u32 b1) {
    asm volatile(
        "mma.sync.aligned.m16n8k16.row.col.f32.f16.f16.f32 "
        "{%0,%1,%2,%3},{%4,%5,%6,%7},{%8,%9},{%0,%1,%2,%3};"
        : "+f"(d[0]), "+f"(d[1]), "+f"(d[2]), "+f"(d[3])
        : "r"(A.x), "r"(A.y), "r"(A.z), "r"(A.w), "r"(b0), "r"(b1));
}

// weight element accessors (row-major [out][k] inputs)
__device__ __forceinline__ float w0_at(const float* W, int o, int k) {
    return (k < 140) ? W[o * 140 + k] : 0.f;
}
__device__ __forceinline__ float wh_at(const float* f1, const float* f2,
                                       const float* ta, const float* tb, int o, int k) {
    if (o < 128) return f1[o * 256 + k];
    if (o < 256) return f2[(o - 128) * 256 + k];
    return ta[(o - 256) * 256 + k] + tb[(o - 256) * 256 + k];
}

// ---------------- fragment precompute ----------------
__global__ void k_prep(const float* __restrict__ Wb0, const float* __restrict__ Wb1,
                       const float* __restrict__ Wff1, const float* __restrict__ Wff2,
                       const float* __restrict__ Wta, const float* __restrict__ Wtb,
                       const float* __restrict__ bff1, const float* __restrict__ bff2,
                       const float* __restrict__ bta, const float* __restrict__ btb) {
    int idx = blockIdx.x * blockDim.x + threadIdx.x;
    const int N0 = 16 * 9 * 32, N1 = 16 * 16 * 32, NH = 24 * 16 * 32;
    if (idx < N0 + N1 + NH) {
        int which, tile, ks, l, i = idx;
        if (i < N0)            { which = 0; tile = i / (9 * 32);  ks = (i / 32) % 9; }
        else if (i < N0 + N1)  { which = 1; i -= N0; tile = i / (16 * 32); ks = (i / 32) % 16; }
        else                   { which = 2; i -= N0 + N1; tile = i / (16 * 32); ks = (i / 32) % 16; }
        l = i % 32;
        int g = l / 4, ti = l % 4;
        int r0 = tile * 16 + g, k0 = ks * 16 + ti * 2;
        float v[8];
        for (int j = 0; j < 8; j++) {
            int ro = r0 + ((j == 1 || j == 3 || j == 5 || j == 7) ? 8 : 0);
            int kk = k0 + (j >> 2) * 8 + (j & 1);
            // order: a0:(r0,k0),(r0,k0+1) a1:(r0+8,k0),(r0+8,k0+1) a2:(r0,k0+8).. a3:(r0+8,k0+8)..
            (void)ro; (void)kk; v[j] = 0.f;
        }
        // explicit fills (clearer than the loop above)
        float e[4][2];
        for (int half = 0; half < 2; half++) {       // a0/a1 then a2/a3 (k offset +8)
            for (int rr = 0; rr < 2; rr++) {         // row g then g+8
                for (int cc = 0; cc < 2; cc++) {
                    int o = r0 + rr * 8, k = k0 + half * 8 + cc;
                    float w;
                    if (which == 0)      w = w0_at(Wb0, o, k);
                    else if (which == 1) w = Wb1[o * 256 + k];
                    else                 w = wh_at(Wff1, Wff2, Wta, Wtb, o, k);
                    e[half * 2 + rr][cc] = w;
                }
            }
        }
        uint4 out;
        out.x = hpack(e[0][0], e[0][1]);  // a0
        out.y = hpack(e[1][0], e[1][1]);  // a1
        out.z = hpack(e[2][0], e[2][1]);  // a2
        out.w = hpack(e[3][0], e[3][1]);  // a3
        if (which == 0)      g_W0f[idx] = out;
        else if (which == 1) g_W1f[idx - N0] = out;
        else                 g_Hf[idx - N0 - N1] = out;
    } else if (idx < N0 + N1 + NH + 384) {
        int j = idx - N0 - N1 - NH;
        float b;
        if (j < 128)      b = bff1[j];
        else if (j < 256) b = bff2[j - 128];
        else              b = bta[j - 256] + btb[j - 256];
        g_bh[j] = b;
    }
}

// ---------------- collapsed _sff operators (transposed) ----------------
__device__ __forceinline__ float sff_contrib(const float* __restrict__ conv,
                                             const float* __restrict__ lin,
                                             int p, int seg, int pad, int so, int si) {
    int phase = so % p, q = so / p;
    float acc = 0.f;
    for (int kk = 0; kk < seg; ++kk) {
        int d = si - (kk * p + phase);
        float c = 0.f;
        if (d >= -pad && d <= pad) c = conv[d + pad];
        if (d == 0) c += 1.f;
        acc += lin[q * seg + kk] * c;
    }
    return acc;
}

__global__ void k_build_T(const float* __restrict__ c3, const float* __restrict__ l3,
                          const float* __restrict__ c6, const float* __restrict__ l6,
                          const float* __restrict__ c12, const float* __restrict__ l12,
                          const float* __restrict__ c24, const float* __restrict__ l24) {
    int idx = blockIdx.x * blockDim.x + threadIdx.x;
    if (idx >= 3 * S2_) return;
    int L = idx / S2_, r = idx % S2_;
    int so = r / S_, si = r % S_;
    float a = sff_contrib(c3 + L * 3, l3 + L * 56 * 56, 3, 56, 1, so, si)
            + sff_contrib(c6 + L * 7, l6 + L * 28 * 28, 6, 28, 3, so, si)
            + sff_contrib(c12 + L * 13, l12 + L * 14 * 14, 12, 14, 6, so, si)
            + sff_contrib(c24 + L * 25, l24 + L * 7 * 7, 24, 7, 12, so, si);
    g_T[L * S2_ + si * S_ + so] = 0.25f * a;
}

__global__ void k_twf(const float* __restrict__ Wfits) {
    int idx = blockIdx.x * blockDim.x + threadIdx.x;
    if (idx >= 3 * S2_) return;
    int c = idx / S2_, r = idx % S2_;
    int s = r / S_, p = r % S_;
    g_WfT[c * S2_ + s * S_ + p] = Wfits[c * S2_ + p * S_ + s];
}

__global__ void k_mean(const float* __restrict__ x) {
    int w = (blockIdx.x * blockDim.x + threadIdx.x) >> 5;
    int lane = threadIdx.x & 31;
    if (w >= B_ * F_) return;
    const float* p = x + w * S_;
    float s = 0.f;
    for (int i = lane; i < S_; i += 32) s += p[i];
#pragma unroll
    for (int o = 16; o; o >>= 1) s += __shfl_xor_sync(0xffffffffu, s, o);
    if (!lane) g_mean[w] = s * (1.f / (float)S_);
}

// ---------------- fused front ----------------
__global__ void k_front(const float* __restrict__ x) {
    __shared__ float xs[S_][F_];
    __shared__ float x1s[S_][4];
    int b = blockIdx.x, t = threadIdx.x;
    for (int i = t; i < S_ * F_; i += blockDim.x) {
        int si = i / F_, f = i % F_;
        xs[si][f] = x[b * F_ * S_ + f * S_ + si] - g_mean[b * F_ + f];
    }
    __syncthreads();
    if (t < S_) {
        float acc[F_];
#pragma unroll
        for (int f = 0; f < F_; f++) acc[f] = 0.f;
        for (int si = 0; si < S_; ++si) {
            float tw = g_T[si * S_ + t];
#pragma unroll
            for (int f = 0; f < F_; f++) acc[f] = fmaf(tw, xs[si][f], acc[f]);
        }
        float* o = g_x1 + (b * S_ + t) * F_;
#pragma unroll
        for (int f = 0; f < F_; f++) o[f] = acc[f];
        x1s[t][0] = acc[0]; x1s[t][1] = acc[1]; x1s[t][2] = acc[2];
    }
    __syncthreads();
    if (t < S_) {
        float a2[3] = {0.f, 0.f, 0.f}, a3[3] = {0.f, 0.f, 0.f};
        for (int si = 0; si < S_; ++si) {
            float t1 = g_T[S2_ + si * S_ + t];
            float t2 = g_T[2 * S2_ + si * S_ + t];
#pragma unroll
            for (int c = 0; c < 3; c++) {
                a2[c] = fmaf(t1, x1s[si][c], a2[c]);
                a3[c] = fmaf(t2, x1s[si][c], a3[c]);
            }
        }
#pragma unroll
        for (int c = 0; c < 3; c++) {
            g_x2[(b * S_ + t) * 3 + c] = a2[c];
            g_x3[(b * S_ + t) * 3 + c] = a3[c];
        }
    }
}

// ---------------- CfC recurrence: tensor-core version ----------------
// SMEM strides (elements): in0 168 halfs/row, za/zb 264 halfs/row, hdro 392 floats/row
__global__ void __launch_bounds__(256, 1) k_rnn(const float* __restrict__ bb0,
                                                const float* __restrict__ bb1) {
    extern __shared__ __align__(16) char s[];
    uint4*  sW0  = (uint4*)s;                      // 73728 B
    uint4*  sW1  = (uint4*)(s + 73728);            // 131072 B
    __half* in0  = (__half*)(s + 204800);          // 8*168*2 = 2688
    __half* za   = (__half*)(s + 207488);          // 8*264*2 = 4224
    __half* zb   = (__half*)(s + 211712);          // 4224
    float*  hdro = (float*)(s + 215936);           // 8*392*4 = 12544
    float*  sb0  = (float*)(s + 228480);           // 1024
    float*  sb1  = (float*)(s + 229504);           // 1024
    float*  sbh  = (float*)(s + 230528);           // 1536  (end 232064)

    const int t = threadIdx.x;
    const int w = t >> 5, l = t & 31, g = l >> 2, ti = l & 3;
    const int bb = blockIdx.x * ROWS;

    // stage weights + biases, zero act buffers
    for (int i = t; i < 16 * 9 * 32; i += 256) sW0[i] = g_W0f[i];
    for (int i = t; i < 16 * 16 * 32; i += 256) sW1[i] = g_W1f[i];
    sb0[t] = bb0[t];
    sb1[t] = bb1[t];
    for (int i = t; i < 384; i += 256) sbh[i] = g_bh[i];
    for (int i = t; i < ROWS * 168; i += 256) in0[i] = __float2half(0.f);
    for (int i = t; i < ROWS * 264; i += 256) { za[i] = __float2half(0.f); zb[i] = __float2half(0.f); }
    // initial x (step 0)
    for (int i = t; i < ROWS * F_; i += 256) {
        int r = i / F_, f = i % F_;
        in0[r * 168 + f] = __float2half(g_x1[(bb + r) * S_ * F_ + f]);
    }

    const int tl0 = 2 * w;      // L0/L1 tiles: tl0, tl0+1
    const int th0 = 3 * w;      // head tiles: th0..th0+2

    for (int step = 0; step < S_; ++step) {
        __syncthreads();  // in0 ready

        // ---- L0: 256 outs, K=144 (9 ksteps) ----
        {
            float d0[4], d1[4];
            float bA = sb0[tl0 * 16 + g], bA8 = sb0[tl0 * 16 + g + 8];
            float bB = sb0[(tl0 + 1) * 16 + g], bB8 = sb0[(tl0 + 1) * 16 + g + 8];
            d0[0] = d0[1] = bA; d0[2] = d0[3] = bA8;
            d1[0] = d1[1] = bB; d1[2] = d1[3] = bB8;
#pragma unroll
            for (int ks = 0; ks < 9; ks++) {
                u32 b0 = *(const u32*)&in0[g * 168 + ks * 16 + ti * 2];
                u32 b1 = *(const u32*)&in0[g * 168 + ks * 16 + ti * 2 + 8];
                mma16816(d0, sW0[(tl0 * 9 + ks) * 32 + l], b0, b1);
                mma16816(d1, sW0[((tl0 + 1) * 9 + ks) * 32 + l], b0, b1);
            }
            int o0 = tl0 * 16 + g, o1 = (tl0 + 1) * 16 + g;
            int ra = ti * 2, rb = ti * 2 + 1;
            za[ra * 264 + o0]     = __float2half(siluf(d0[0]));
            za[rb * 264 + o0]     = __float2half(siluf(d0[1]));
            za[ra * 264 + o0 + 8] = __float2half(siluf(d0[2]));
            za[rb * 264 + o0 + 8] = __float2half(siluf(d0[3]));
            za[ra * 264 + o1]     = __float2half(siluf(d1[0]));
            za[rb * 264 + o1]     = __float2half(siluf(d1[1]));
            za[ra * 264 + o1 + 8] = __float2half(siluf(d1[2]));
            za[rb * 264 + o1 + 8] = __float2half(siluf(d1[3]));
        }
        __syncthreads();

        // ---- L1: 256 outs, K=256 (16 ksteps) ----
        {
            float d0[4], d1[4];
            float bA = sb1[tl0 * 16 + g], bA8 = sb1[tl0 * 16 + g + 8];
            float bB = sb1[(tl0 + 1) * 16 + g], bB8 = sb1[(tl0 + 1) * 16 + g + 8];
            d0[0] = d0[1] = bA; d0[2] = d0[3] = bA8;
            d1[0] = d1[1] = bB; d1[2] = d1[3] = bB8;
#pragma unroll
            for (int ks = 0; ks < 16; ks++) {
                u32 b0 = *(const u32*)&za[g * 264 + ks * 16 + ti * 2];
                u32 b1 = *(const u32*)&za[g * 264 + ks * 16 + ti * 2 + 8];
                mma16816(d0, sW1[(tl0 * 16 + ks) * 32 + l], b0, b1);
                mma16816(d1, sW1[((tl0 + 1) * 16 + ks) * 32 + l], b0, b1);
            }
            int o0 = tl0 * 16 + g, o1 = (tl0 + 1) * 16 + g;
            int ra = ti * 2, rb = ti * 2 + 1;
            zb[ra * 264 + o0]     = __float2half(siluf(d0[0]));
            zb[rb * 264 + o0]     = __float2half(siluf(d0[1]));
            zb[ra * 264 + o0 + 8] = __float2half(siluf(d0[2]));
            zb[rb * 264 + o0 + 8] = __float2half(siluf(d0[3]));
            zb[ra * 264 + o1]     = __float2half(siluf(d1[0]));
            zb[rb * 264 + o1]     = __float2half(siluf(d1[1]));
            zb[ra * 264 + o1 + 8] = __float2half(siluf(d1[2]));
            zb[rb * 264 + o1 + 8] = __float2half(siluf(d1[3]));
        }
        __syncthreads();

        // ---- head: 384 outs, K=256, weights streamed from L2, 1-deep prefetch ----
        {
            float e0[4], e1[4], e2[4];
            e0[0] = e0[1] = sbh[th0 * 16 + g];       e0[2] = e0[3] = sbh[th0 * 16 + g + 8];
            e1[0] = e1[1] = sbh[(th0 + 1) * 16 + g]; e1[2] = e1[3] = sbh[(th0 + 1) * 16 + g + 8];
            e2[0] = e2[1] = sbh[(th0 + 2) * 16 + g]; e2[2] = e2[3] = sbh[(th0 + 2) * 16 + g + 8];
            uint4 A0 = g_Hf[(th0 * 16 + 0) * 32 + l];
            uint4 A1 = g_Hf[((th0 + 1) * 16 + 0) * 32 + l];
            uint4 A2 = g_Hf[((th0 + 2) * 16 + 0) * 32 + l];
#pragma unroll
            for (int ks = 0; ks < 16; ks++) {
                uint4 N0v, N1v, N2v;
                if (ks < 15) {
                    N0v = g_Hf[(th0 * 16 + ks + 1) * 32 + l];
                    N1v = g_Hf[((th0 + 1) * 16 + ks + 1) * 32 + l];
                    N2v = g_Hf[((th0 + 2) * 16 + ks + 1) * 32 + l];
                }
                u32 b0 = *(const u32*)&zb[g * 264 + ks * 16 + ti * 2];
                u32 b1 = *(const u32*)&zb[g * 264 + ks * 16 + ti * 2 + 8];
                mma16816(e0, A0, b0, b1);
                mma16816(e1, A1, b0, b1);
                mma16816(e2, A2, b0, b1);
                if (ks < 15) { A0 = N0v; A1 = N1v; A2 = N2v; }
            }
            int ra = ti * 2, rb = ti * 2 + 1;
            int o0 = th0 * 16 + g, o1 = o0 + 16, o2 = o0 + 32;
            hdro[ra * 392 + o0] = e0[0]; hdro[rb * 392 + o0] = e0[1];
            hdro[ra * 392 + o0 + 8] = e0[2]; hdro[rb * 392 + o0 + 8] = e0[3];
            hdro[ra * 392 + o1] = e1[0]; hdro[rb * 392 + o1] = e1[1];
            hdro[ra * 392 + o1 + 8] = e1[2]; hdro[rb * 392 + o1 + 8] = e1[3];
            hdro[ra * 392 + o2] = e2[0]; hdro[rb * 392 + o2] = e2[1];
            hdro[ra * 392 + o2 + 8] = e2[2]; hdro[rb * 392 + o2 + 8] = e2[3];
        }
        __syncthreads();

        // ---- combine + feedback + store h; prefetch next x ----
        int nsf = (step + 1 < S_) ? step + 1 : S_ - 1;
#pragma unroll
        for (int it = 0; it < 4; it++) {
            int i = t + 256 * it;
            int row = i >> 7, j = i & 127;
            float f1 = tanhf_fast(hdro[row * 392 + j]);
            float f2 = tanhf_fast(hdro[row * 392 + 128 + j]);
            float sg = sigf(hdro[row * 392 + 256 + j]);
            float h = f1 + sg * (f2 - f1);
            in0[row * 168 + 12 + j] = __float2half(h);
            g_hs[((bb + row) * S_ + step) * H_ + j] = h;
        }
        for (int i = t; i < ROWS * F_; i += 256) {
            int r = i / F_, f = i % F_;
            in0[r * 168 + f] = __float2half(g_x1[((bb + r) * S_ + nsf) * F_ + f]);
        }
    }
}

// ---------------- fused back ----------------
__global__ void k_back(const float* __restrict__ Wfc, const float* __restrict__ bfc,
                       float* __restrict__ out) {
    __shared__ float r1s[S_][4];
    int b = blockIdx.x, t = threadIdx.x;
    int w = t >> 5, lane = t & 31;
    for (int s = w; s < S_; s += 8) {
        const float* h = g_hs + (size_t)(b * S_ + s) * H_;
        float a0 = 0.f, a1 = 0.f, a2 = 0.f;
        for (int i = lane; i < H_; i += 32) {
            float hv = h[i];
            a0 = fmaf(hv, Wfc[i], a0);
            a1 = fmaf(hv, Wfc[H_ + i], a1);
            a2 = fmaf(hv, Wfc[2 * H_ + i], a2);
        }
#pragma unroll
        for (int o = 16; o; o >>= 1) {
            a0 += __shfl_xor_sync(0xffffffffu, a0, o);
            a1 += __shfl_xor_sync(0xffffffffu, a1, o);
            a2 += __shfl_xor_sync(0xffffffffu, a2, o);
        }
        if (!lane) {
            r1s[s][0] = a0 + bfc[0] + g_x3[(b * S_ + s) * 3 + 0];
            r1s[s][1] = a1 + bfc[1] + g_x3[(b * S_ + s) * 3 + 1];
            r1s[s][2] = a2 + bfc[2] + g_x3[(b * S_ + s) * 3 + 2];
        }
    }
    __syncthreads();
    if (t < S_) {
        float a0 = g_mean[b * F_ + 0] + g_x2[(b * S_ + t) * 3 + 0];
        float a1 = g_mean[b * F_ + 1] + g_x2[(b * S_ + t) * 3 + 1];
        float a2 = g_mean[b * F_ + 2] + g_x2[(b * S_ + t) * 3 + 2];
        for (int s = 0; s < S_; ++s) {
            a0 = fmaf(r1s[s][0], g_WfT[0 * S2_ + s * S_ + t], a0);
            a1 = fmaf(r1s[s][1], g_WfT[1 * S2_ + s * S_ + t], a1);
            a2 = fmaf(r1s[s][2], g_WfT[2 * S2_ + s * S_ + t], a2);
        }
        float* o = out + (b * S_ + t) * 3;
        o[0] = a0; o[1] = a1; o[2] = a2;
    }
}

// ---------------- launch ----------------
extern "C" void kernel_launch(void* const* d_in, const int* in_sizes, int n_in,
                              void* d_out, int out_size) {
    const float* x     = (const float*)d_in[0];
    const float* c3    = (const float*)d_in[1];
    const float* l3    = (const float*)d_in[2];
    const float* c6    = (const float*)d_in[3];
    const float* l6    = (const float*)d_in[4];
    const float* c12   = (const float*)d_in[5];
    const float* l12   = (const float*)d_in[6];
    const float* c24   = (const float*)d_in[7];
    const float* l24   = (const float*)d_in[8];
    const float* Wb0   = (const float*)d_in[9];
    const float* bb0   = (const float*)d_in[10];
    const float* Wb1   = (const float*)d_in[11];
    const float* bb1   = (const float*)d_in[12];
    const float* Wff1  = (const float*)d_in[13];
    const float* bff1  = (const float*)d_in[14];
    const float* Wff2  = (const float*)d_in[15];
    const float* bff2  = (const float*)d_in[16];
    const float* Wta   = (const float*)d_in[17];
    const float* bta   = (const float*)d_in[18];
    const float* Wtb   = (const float*)d_in[19];
    const float* btb   = (const float*)d_in[20];
    const float* Wfc   = (const float*)d_in[21];
    const float* bfc   = (const float*)d_in[22];
    const float* Wfits = (const float*)d_in[23];
    float* out = (float*)d_out;
    (void)bff1; (void)bff2; (void)bta; (void)btb;

    const int SMEM_RNN = 232064;
    cudaFuncSetAttribute(k_rnn, cudaFuncAttributeMaxDynamicSharedMemorySize, SMEM_RNN);

    const int NPREP = 16 * 9 * 32 + 16 * 16 * 32 + 24 * 16 * 32 + 384;
    k_prep<<<(NPREP + 255) / 256, 256>>>(Wb0, Wb1, Wff1, Wff2, Wta, Wtb,
                                         bff1, bff2, bta, btb);
    k_build_T<<<(3 * S2_ + 255) / 256, 256>>>(c3, l3, c6, l6, c12, l12, c24, l24);
    k_twf<<<(3 * S2_ + 255) / 256, 256>>>(Wfits);
    k_mean<<<(B_ * F_ * 32 + 255) / 256, 256>>>(x);
    k_front<<<B_, 192>>>(x);
    k_rnn<<<NCTA, 256, SMEM_RNN>>>(bb0, bb1);
    k_back<<<B_, 256>>>(Wfc, bfc, out);
}

// round 7
// speedup vs baseline: 3.6641x; 1.1731x over previous
#include <cuda_runtime.h>
#include <cuda_fp16.h>

#define B_ 512
#define S_ 168
#define F_ 12
#define H_ 128
#define O_ 3
#define S2_ (S_ * S_)
#define ROWS 8

typedef unsigned int u32;

// ---------------- device scratch ----------------
__device__ uint4 g_W0f[16 * 9 * 32];    // L0 fragments [tile][kstep][lane]
__device__ uint4 g_W1f[16 * 16 * 32];   // L1 fragments
__device__ uint4 g_Hf[24 * 16 * 32];    // head fragments (re-ordered blocks)
__device__ float g_bh[384];             // merged head bias (re-ordered)
__device__ float g_T[3 * S2_];          // transposed [L][si][so]
__device__ float g_WfT[3 * S2_];        // transposed [c][s][p]
__device__ float g_mean[B_ * F_];
__device__ float g_x1[B_ * S_ * F_];
__device__ float g_x2[B_ * S_ * O_];
__device__ float g_x3[B_ * S_ * O_];
__device__ float g_hs[B_ * S_ * H_];

// ---------------- helpers ----------------
__device__ __forceinline__ float siluf(float x) { return __fdividef(x, 1.f + __expf(-x)); }
__device__ __forceinline__ float sigf(float x)  { return __fdividef(1.f, 1.f + __expf(-x)); }
__device__ __forceinline__ float tanhf_fast(float x) {
    float e = __expf(2.f * x);
    return 1.f - __fdividef(2.f, e + 1.f);
}
__device__ __forceinline__ u32 hpack(float a, float b) {
    __half2 h = __floats2half2_rn(a, b);
    return *reinterpret_cast<u32*>(&h);
}
__device__ __forceinline__ void mma16816(float* d, uint4 A, u32 b0, u32 b1) {
    asm volatile(
        "mma.sync.aligned.m16n8k16.row.col.f32.f16.f16.f32 "
        "{%0,%1,%2,%3},{%4,%5,%6,%7},{%8,%9},{%0,%1,%2,%3};"
        : "+f"(d[0]), "+f"(d[1]), "+f"(d[2]), "+f"(d[3])
        : "r"(A.x), "r"(A.y), "r"(A.z), "r"(A.w), "r"(b0), "r"(b1));
}
#define CLUSTER_SYNC() do { \
    asm volatile("barrier.cluster.arrive.aligned;" ::: "memory"); \
    asm volatile("barrier.cluster.wait.aligned;" ::: "memory"); } while (0)

__device__ __forceinline__ void sts_r16(u32 a, __half v) {
    asm volatile("st.shared::cluster.b16 [%0], %1;" :: "r"(a), "h"(__half_as_ushort(v)));
}

// weight element accessors
__device__ __forceinline__ float w0_at(const float* W, int o, int k) {
    return (k < 140) ? W[o * 140 + k] : 0.f;
}
// NEW head ordering: block r (192 rows) = [ff1(64r:64r+64); ff2(64r:64r+64); gate(64r:64r+64)]
__device__ __forceinline__ float wh_at(const float* f1, const float* f2,
                                       const float* ta, const float* tb, int m, int k) {
    int blk = m / 192, o = m % 192, base = blk * 64;
    if (o < 64)  return f1[(base + o) * 256 + k];
    if (o < 128) return f2[(base + o - 64) * 256 + k];
    return ta[(base + o - 128) * 256 + k] + tb[(base + o - 128) * 256 + k];
}

// ---------------- fragment precompute ----------------
__global__ void k_prep(const float* __restrict__ Wb0, const float* __restrict__ Wb1,
                       const float* __restrict__ Wff1, const float* __restrict__ Wff2,
                       const float* __restrict__ Wta, const float* __restrict__ Wtb,
                       const float* __restrict__ bff1, const float* __restrict__ bff2,
                       const float* __restrict__ bta, const float* __restrict__ btb) {
    int idx = blockIdx.x * blockDim.x + threadIdx.x;
    const int N0 = 16 * 9 * 32, N1 = 16 * 16 * 32, NH = 24 * 16 * 32;
    if (idx < N0 + N1 + NH) {
        int which, tile, ks, l, i = idx;
        if (i < N0)           { which = 0; tile = i / (9 * 32);  ks = (i / 32) % 9; }
        else if (i < N0 + N1) { which = 1; i -= N0; tile = i / (16 * 32); ks = (i / 32) % 16; }
        else                  { which = 2; i -= N0 + N1; tile = i / (16 * 32); ks = (i / 32) % 16; }
        l = i % 32;
        int g = l / 4, ti = l % 4;
        int r0 = tile * 16 + g, k0 = ks * 16 + ti * 2;
        float e[4][2];
        for (int half = 0; half < 2; half++) {
            for (int rr = 0; rr < 2; rr++) {
                for (int cc = 0; cc < 2; cc++) {
                    int o = r0 + rr * 8, k = k0 + half * 8 + cc;
                    float wv;
                    if (which == 0)      wv = w0_at(Wb0, o, k);
                    else if (which == 1) wv = Wb1[o * 256 + k];
                    else                 wv = wh_at(Wff1, Wff2, Wta, Wtb, o, k);
                    e[half * 2 + rr][cc] = wv;
                }
            }
        }
        uint4 out;
        out.x = hpack(e[0][0], e[0][1]);
        out.y = hpack(e[1][0], e[1][1]);
        out.z = hpack(e[2][0], e[2][1]);
        out.w = hpack(e[3][0], e[3][1]);
        if (which == 0)      g_W0f[idx] = out;
        else if (which == 1) g_W1f[idx - N0] = out;
        else                 g_Hf[idx - N0 - N1] = out;
    } else if (idx < N0 + N1 + NH + 384) {
        int m = idx - N0 - N1 - NH;
        int blk = m / 192, o = m % 192, base = blk * 64;
        float b;
        if (o < 64)       b = bff1[base + o];
        else if (o < 128) b = bff2[base + o - 64];
        else              b = bta[base + o - 128] + btb[base + o - 128];
        g_bh[m] = b;
    }
}

// ---------------- collapsed _sff operators (transposed) ----------------
__device__ __forceinline__ float sff_contrib(const float* __restrict__ conv,
                                             const float* __restrict__ lin,
                                             int p, int seg, int pad, int so, int si) {
    int phase = so % p, q = so / p;
    float acc = 0.f;
    for (int kk = 0; kk < seg; ++kk) {
        int d = si - (kk * p + phase);
        float c = 0.f;
        if (d >= -pad && d <= pad) c = conv[d + pad];
        if (d == 0) c += 1.f;
        acc += lin[q * seg + kk] * c;
    }
    return acc;
}

__global__ void k_build_T(const float* __restrict__ c3, const float* __restrict__ l3,
                          const float* __restrict__ c6, const float* __restrict__ l6,
                          const float* __restrict__ c12, const float* __restrict__ l12,
                          const float* __restrict__ c24, const float* __restrict__ l24) {
    int idx = blockIdx.x * blockDim.x + threadIdx.x;
    if (idx >= 3 * S2_) return;
    int L = idx / S2_, r = idx % S2_;
    int so = r / S_, si = r % S_;
    float a = sff_contrib(c3 + L * 3, l3 + L * 56 * 56, 3, 56, 1, so, si)
            + sff_contrib(c6 + L * 7, l6 + L * 28 * 28, 6, 28, 3, so, si)
            + sff_contrib(c12 + L * 13, l12 + L * 14 * 14, 12, 14, 6, so, si)
            + sff_contrib(c24 + L * 25, l24 + L * 7 * 7, 24, 7, 12, so, si);
    g_T[L * S2_ + si * S_ + so] = 0.25f * a;
}

__global__ void k_twf(const float* __restrict__ Wfits) {
    int idx = blockIdx.x * blockDim.x + threadIdx.x;
    if (idx >= 3 * S2_) return;
    int c = idx / S2_, r = idx % S2_;
    int s = r / S_, p = r % S_;
    g_WfT[c * S2_ + s * S_ + p] = Wfits[c * S2_ + p * S_ + s];
}

__global__ void k_mean(const float* __restrict__ x) {
    int w = (blockIdx.x * blockDim.x + threadIdx.x) >> 5;
    int lane = threadIdx.x & 31;
    if (w >= B_ * F_) return;
    const float* p = x + w * S_;
    float s = 0.f;
    for (int i = lane; i < S_; i += 32) s += p[i];
#pragma unroll
    for (int o = 16; o; o >>= 1) s += __shfl_xor_sync(0xffffffffu, s, o);
    if (!lane) g_mean[w] = s * (1.f / (float)S_);
}

// ---------------- fused front ----------------
__global__ void k_front(const float* __restrict__ x) {
    __shared__ float xs[S_][F_];
    __shared__ float x1s[S_][4];
    int b = blockIdx.x, t = threadIdx.x;
    for (int i = t; i < S_ * F_; i += blockDim.x) {
        int si = i / F_, f = i % F_;
        xs[si][f] = x[b * F_ * S_ + f * S_ + si] - g_mean[b * F_ + f];
    }
    __syncthreads();
    if (t < S_) {
        float acc[F_];
#pragma unroll
        for (int f = 0; f < F_; f++) acc[f] = 0.f;
        for (int si = 0; si < S_; ++si) {
            float tw = g_T[si * S_ + t];
#pragma unroll
            for (int f = 0; f < F_; f++) acc[f] = fmaf(tw, xs[si][f], acc[f]);
        }
        float* o = g_x1 + (b * S_ + t) * F_;
#pragma unroll
        for (int f = 0; f < F_; f++) o[f] = acc[f];
        x1s[t][0] = acc[0]; x1s[t][1] = acc[1]; x1s[t][2] = acc[2];
    }
    __syncthreads();
    if (t < S_) {
        float a2[3] = {0.f, 0.f, 0.f}, a3[3] = {0.f, 0.f, 0.f};
        for (int si = 0; si < S_; ++si) {
            float t1 = g_T[S2_ + si * S_ + t];
            float t2 = g_T[2 * S2_ + si * S_ + t];
#pragma unroll
            for (int c = 0; c < 3; c++) {
                a2[c] = fmaf(t1, x1s[si][c], a2[c]);
                a3[c] = fmaf(t2, x1s[si][c], a3[c]);
            }
        }
#pragma unroll
        for (int c = 0; c < 3; c++) {
            g_x2[(b * S_ + t) * 3 + c] = a2[c];
            g_x3[(b * S_ + t) * 3 + c] = a3[c];
        }
    }
}

// ---------------- CfC recurrence: cluster-2 output-split, all-SMEM weights ----
// SMEM layout (bytes):
//   [0, 36864)        sW0  half: 8 tiles x 9 ks x 32 lanes x uint4
//   [36864, 102400)   sW1  half: 8 x 16 x 32
//   [102400, 200704)  sHf  half: 12 x 16 x 32
//   [200704, 203392)  in0  8 rows x 168 halfs
//   [203392, 207616)  za   8 x 264 halfs
//   [207616, 211840)  zb   8 x 264 halfs
//   [211840, 218240)  hdro 8 x 200 floats (192 used)
//   [218240, 219264)  sb0  256 f
//   [219264, 220288)  sb1  256 f
//   [220288, 221824)  sbh  384 f
__global__ void __launch_bounds__(256, 1) __cluster_dims__(2, 1, 1)
k_rnn(const float* __restrict__ bb0, const float* __restrict__ bb1) {
    extern __shared__ __align__(16) char s[];
    uint4*  sW0  = (uint4*)(s);
    uint4*  sW1  = (uint4*)(s + 36864);
    uint4*  sHf  = (uint4*)(s + 102400);
    __half* in0  = (__half*)(s + 200704);
    __half* za   = (__half*)(s + 203392);
    __half* zb   = (__half*)(s + 207616);
    float*  hdro = (float*)(s + 211840);
    float*  sb0  = (float*)(s + 218240);
    float*  sb1  = (float*)(s + 219264);
    float*  sbh  = (float*)(s + 220288);

    const int t = threadIdx.x, w = t >> 5, l = t & 31, g = l >> 2, ti = l & 3;
    u32 rank;
    asm("mov.u32 %0, %%cluster_ctarank;" : "=r"(rank));
    const u32 peer = rank ^ 1u;
    const int bb = (blockIdx.x >> 1) * ROWS;

    u32 base;
    asm("{ .reg .u64 a; cvta.to.shared.u64 a, %1; cvt.u32.u64 %0, a; }" : "=r"(base) : "l"(s));
    u32 in0_l = base + 200704, za_l = base + 203392, zb_l = base + 207616;
    u32 in0_r, za_r, zb_r;
    asm("mapa.shared::cluster.u32 %0, %1, %2;" : "=r"(in0_r) : "r"(in0_l), "r"(peer));
    asm("mapa.shared::cluster.u32 %0, %1, %2;" : "=r"(za_r) : "r"(za_l), "r"(peer));
    asm("mapa.shared::cluster.u32 %0, %1, %2;" : "=r"(zb_r) : "r"(zb_l), "r"(peer));

    // stage this CTA's half of each weight matrix + biases
    {
        const uint4* p0 = g_W0f + rank * 2304;
        for (int i = t; i < 2304; i += 256) sW0[i] = p0[i];
        const uint4* p1 = g_W1f + rank * 4096;
        for (int i = t; i < 4096; i += 256) sW1[i] = p1[i];
        const uint4* ph = g_Hf + rank * 6144;
        for (int i = t; i < 6144; i += 256) sHf[i] = ph[i];
    }
    sb0[t] = bb0[t];
    sb1[t] = bb1[t];
    for (int i = t; i < 384; i += 256) sbh[i] = g_bh[i];
    for (int i = t; i < ROWS * 168; i += 256) in0[i] = __float2half(0.f);
    __syncthreads();
    for (int i = t; i < ROWS * F_; i += 256) {
        int r = i / F_, f = i % F_;
        in0[r * 168 + f] = __float2half(g_x1[(bb + r) * S_ * F_ + f]);
    }

    const int ra = 2 * ti, rb = 2 * ti + 1;
    const int hb = 192 * (int)rank;     // head bias block offset

    for (int step = 0; step < S_; ++step) {
        CLUSTER_SYNC();   // B1: in0 (x + both h halves) complete on both CTAs

        // prefetch next step's x into registers (written after B2)
        float xreg = 0.f;
        int xr = 0, xf = 0;
        if (t < ROWS * F_) {
            xr = t / F_; xf = t - xr * F_;
            int ns = (step + 1 < S_) ? step + 1 : S_ - 1;
            xreg = __ldg(&g_x1[((bb + xr) * S_ + ns) * F_ + xf]);
        }

        // ---- L0: this CTA's 128 outs (8 tiles, 1/warp), K=144 ----
        {
            int gob = (8 * (int)rank + w) * 16;
            float d[4];
            d[0] = d[1] = sb0[gob + g];
            d[2] = d[3] = sb0[gob + g + 8];
#pragma unroll
            for (int ks = 0; ks < 9; ks++) {
                u32 b0 = *(const u32*)&in0[g * 168 + ks * 16 + ti * 2];
                u32 b1 = *(const u32*)&in0[g * 168 + ks * 16 + ti * 2 + 8];
                mma16816(d, sW0[(w * 9 + ks) * 32 + l], b0, b1);
            }
            float v0 = siluf(d[0]), v1 = siluf(d[1]), v2 = siluf(d[2]), v3 = siluf(d[3]);
            __half h0 = __float2half(v0), h1 = __float2half(v1);
            __half h2 = __float2half(v2), h3 = __float2half(v3);
            int i0 = ra * 264 + gob + g, i1 = rb * 264 + gob + g;
            za[i0] = h0;     za[i1] = h1;
            za[i0 + 8] = h2; za[i1 + 8] = h3;
            sts_r16(za_r + i0 * 2, h0);       sts_r16(za_r + i1 * 2, h1);
            sts_r16(za_r + (i0 + 8) * 2, h2); sts_r16(za_r + (i1 + 8) * 2, h3);
        }
        CLUSTER_SYNC();   // B2: za complete on both CTAs

        if (t < ROWS * F_) in0[xr * 168 + xf] = __float2half(xreg);

        // ---- L1: this CTA's 128 outs, K=256 ----
        {
            int gob = (8 * (int)rank + w) * 16;
            float d[4];
            d[0] = d[1] = sb1[gob + g];
            d[2] = d[3] = sb1[gob + g + 8];
#pragma unroll
            for (int ks = 0; ks < 16; ks++) {
                u32 b0 = *(const u32*)&za[g * 264 + ks * 16 + ti * 2];
                u32 b1 = *(const u32*)&za[g * 264 + ks * 16 + ti * 2 + 8];
                mma16816(d, sW1[(w * 16 + ks) * 32 + l], b0, b1);
            }
            float v0 = siluf(d[0]), v1 = siluf(d[1]), v2 = siluf(d[2]), v3 = siluf(d[3]);
            __half h0 = __float2half(v0), h1 = __float2half(v1);
            __half h2 = __float2half(v2), h3 = __float2half(v3);
            int i0 = ra * 264 + gob + g, i1 = rb * 264 + gob + g;
            zb[i0] = h0;     zb[i1] = h1;
            zb[i0 + 8] = h2; zb[i1 + 8] = h3;
            sts_r16(zb_r + i0 * 2, h0);       sts_r16(zb_r + i1 * 2, h1);
            sts_r16(zb_r + (i0 + 8) * 2, h2); sts_r16(zb_r + (i1 + 8) * 2, h3);
        }
        CLUSTER_SYNC();   // B3: zb complete on both CTAs

        // ---- head: this CTA's 192 outs (12 tiles; warps 0-3 take 2, 4-7 take 1) ----
        {
            int ntile = (w < 4) ? 2 : 1;
            for (int sub = 0; sub < ntile; sub++) {
                int lt = (sub == 0) ? w : 8 + w;
                int ob = lt * 16;
                float e[4];
                e[0] = e[1] = sbh[hb + ob + g];
                e[2] = e[3] = sbh[hb + ob + g + 8];
#pragma unroll
                for (int ks = 0; ks < 16; ks++) {
                    u32 b0 = *(const u32*)&zb[g * 264 + ks * 16 + ti * 2];
                    u32 b1 = *(const u32*)&zb[g * 264 + ks * 16 + ti * 2 + 8];
                    mma16816(e, sHf[(lt * 16 + ks) * 32 + l], b0, b1);
                }
                hdro[ra * 200 + ob + g] = e[0];
                hdro[rb * 200 + ob + g] = e[1];
                hdro[ra * 200 + ob + g + 8] = e[2];
                hdro[rb * 200 + ob + g + 8] = e[3];
            }
        }
        __syncthreads();  // hdro ready (local)

        // ---- combine (fully local j-half) + feedback to both CTAs + store h ----
#pragma unroll
        for (int it = 0; it < 2; it++) {
            int i = t + 256 * it;
            int row = i >> 6, j = i & 63;
            float f1 = tanhf_fast(hdro[row * 200 + j]);
            float f2 = tanhf_fast(hdro[row * 200 + 64 + j]);
            float sg = sigf(hdro[row * 200 + 128 + j]);
            float h = f1 + sg * (f2 - f1);
            int jg = 64 * (int)rank + j;
            __half hh = __float2half(h);
            int idx = row * 168 + 12 + jg;
            in0[idx] = hh;
            sts_r16(in0_r + idx * 2, hh);
            g_hs[((bb + row) * S_ + step) * H_ + jg] = h;
        }
    }
    CLUSTER_SYNC();   // peer may still be writing our in0 — don't exit early
}

// ---------------- fused back ----------------
__global__ void k_back(const float* __restrict__ Wfc, const float* __restrict__ bfc,
                       float* __restrict__ out) {
    __shared__ float r1s[S_][4];
    int b = blockIdx.x, t = threadIdx.x;
    int w = t >> 5, lane = t & 31;
    for (int s = w; s < S_; s += 8) {
        const float* h = g_hs + (size_t)(b * S_ + s) * H_;
        float a0 = 0.f, a1 = 0.f, a2 = 0.f;
        for (int i = lane; i < H_; i += 32) {
            float hv = h[i];
            a0 = fmaf(hv, Wfc[i], a0);
            a1 = fmaf(hv, Wfc[H_ + i], a1);
            a2 = fmaf(hv, Wfc[2 * H_ + i], a2);
        }
#pragma unroll
        for (int o = 16; o; o >>= 1) {
            a0 += __shfl_xor_sync(0xffffffffu, a0, o);
            a1 += __shfl_xor_sync(0xffffffffu, a1, o);
            a2 += __shfl_xor_sync(0xffffffffu, a2, o);
        }
        if (!lane) {
            r1s[s][0] = a0 + bfc[0] + g_x3[(b * S_ + s) * 3 + 0];
            r1s[s][1] = a1 + bfc[1] + g_x3[(b * S_ + s) * 3 + 1];
            r1s[s][2] = a2 + bfc[2] + g_x3[(b * S_ + s) * 3 + 2];
        }
    }
    __syncthreads();
    if (t < S_) {
        float a0 = g_mean[b * F_ + 0] + g_x2[(b * S_ + t) * 3 + 0];
        float a1 = g_mean[b * F_ + 1] + g_x2[(b * S_ + t) * 3 + 1];
        float a2 = g_mean[b * F_ + 2] + g_x2[(b * S_ + t) * 3 + 2];
        for (int s = 0; s < S_; ++s) {
            a0 = fmaf(r1s[s][0], g_WfT[0 * S2_ + s * S_ + t], a0);
            a1 = fmaf(r1s[s][1], g_WfT[1 * S2_ + s * S_ + t], a1);
            a2 = fmaf(r1s[s][2], g_WfT[2 * S2_ + s * S_ + t], a2);
        }
        float* o = out + (b * S_ + t) * 3;
        o[0] = a0; o[1] = a1; o[2] = a2;
    }
}

// ---------------- launch ----------------
extern "C" void kernel_launch(void* const* d_in, const int* in_sizes, int n_in,
                              void* d_out, int out_size) {
    const float* x     = (const float*)d_in[0];
    const float* c3    = (const float*)d_in[1];
    const float* l3    = (const float*)d_in[2];
    const float* c6    = (const float*)d_in[3];
    const float* l6    = (const float*)d_in[4];
    const float* c12   = (const float*)d_in[5];
    const float* l12   = (const float*)d_in[6];
    const float* c24   = (const float*)d_in[7];
    const float* l24   = (const float*)d_in[8];
    const float* Wb0   = (const float*)d_in[9];
    const float* bb0   = (const float*)d_in[10];
    const float* Wb1   = (const float*)d_in[11];
    const float* bb1   = (const float*)d_in[12];
    const float* Wff1  = (const float*)d_in[13];
    const float* bff1  = (const float*)d_in[14];
    const float* Wff2  = (const float*)d_in[15];
    const float* bff2  = (const float*)d_in[16];
    const float* Wta   = (const float*)d_in[17];
    const float* bta   = (const float*)d_in[18];
    const float* Wtb   = (const float*)d_in[19];
    const float* btb   = (const float*)d_in[20];
    const float* Wfc   = (const float*)d_in[21];
    const float* bfc   = (const float*)d_in[22];
    const float* Wfits = (const float*)d_in[23];
    float* out = (float*)d_out;

    const int SMEM_RNN = 221824;
    cudaFuncSetAttribute(k_rnn, cudaFuncAttributeMaxDynamicSharedMemorySize, SMEM_RNN);

    const int NPREP = 16 * 9 * 32 + 16 * 16 * 32 + 24 * 16 * 32 + 384;
    k_prep<<<(NPREP + 255) / 256, 256>>>(Wb0, Wb1, Wff1, Wff2, Wta, Wtb,
                                         bff1, bff2, bta, btb);
    k_build_T<<<(3 * S2_ + 255) / 256, 256>>>(c3, l3, c6, l6, c12, l12, c24, l24);
    k_twf<<<(3 * S2_ + 255) / 256, 256>>>(Wfits);
    k_mean<<<(B_ * F_ * 32 + 255) / 256, 256>>>(x);
    k_front<<<B_, 192>>>(x);
    k_rnn<<<128, 256, SMEM_RNN>>>(bb0, bb1);
    k_back<<<B_, 256>>>(Wfc, bfc, out);
}